// round 9
// baseline (speedup 1.0000x reference)
#include <cuda_runtime.h>
#include <cuda_fp16.h>
#include <cstdint>

// ---------------- problem constants ----------------
#define B       64
#define N       4096
#define D       64
#define H       128
#define NS      8
#define ITERS   3
#define EPSA    1e-8f
#define LN_EPS  1e-5f
#define SCALE   0.125f

#define TILE_R  64              // rows per region in kv kernel
#define NB      16              // chunks per batch in attention (256 rows each)
#define DSTR    257             // padded stride for dots/att smem

typedef unsigned long long ull;

// ---------------- device scratch ----------------
__device__ __half g_kh[B*N*D];         // compacted per region, fp16 (phase A)
__device__ float  g_v[B*N*D];          // compacted per region, fp32 (phase C)
__device__ int    g_cnt[B*N/TILE_R];
__device__ float  g_slots[B*NS*D];
__device__ float  g_q[B*NS*D];
__device__ float  g_Pp[B*NB*NS*D];
__device__ float  g_Sp[B*NB*NS];
__device__ ulonglong2 g_wk2v[16*64];   // [d4][c] packed f32x2 pairs
__device__ ulonglong2 g_wv2v[16*64];
__device__ float4 g_WgA[64*64];        // [d][dd] = (Wih_r, Wih_z, Wih_n, Whh_r)
__device__ float2 g_WgB[64*64];        // [d][dd] = (Whh_z, Whh_n)
__device__ float2 g_W1p[64*64];        // [d][h2]
__device__ float2 g_W2p[64*64];        // [h2][dd]
__device__ float2 g_Wqp[32*64];        // [d2][dd]

// ---------------- f32x2 helpers ----------------
__device__ __forceinline__ ull packf2(float x, float y) {
    ull r;
    asm("mov.b64 %0, {%1,%2};" : "=l"(r) : "f"(x), "f"(y));
    return r;
}
__device__ __forceinline__ float2 unpackf2(ull v) {
    float2 f;
    asm("mov.b64 {%0,%1}, %2;" : "=f"(f.x), "=f"(f.y) : "l"(v));
    return f;
}
__device__ __forceinline__ ull ffma2(ull a, ull b, ull c) {
    ull d;
    asm("fma.rn.f32x2 %0, %1, %2, %3;" : "=l"(d) : "l"(a), "l"(b), "l"(c));
    return d;
}

// dot of 16 halves (two uint4) against q[0..15]
__device__ __forceinline__ float doth16(uint4 u0, uint4 u1, const float* q) {
    const __half2* h0 = reinterpret_cast<const __half2*>(&u0);
    const __half2* h1 = reinterpret_cast<const __half2*>(&u1);
    float acc = 0.f;
    #pragma unroll
    for (int i = 0; i < 4; ++i) {
        float2 f = __half22float2(h0[i]);
        acc += f.x*q[2*i] + f.y*q[2*i+1];
    }
    #pragma unroll
    for (int i = 0; i < 4; ++i) {
        float2 f = __half22float2(h1[i]);
        acc += f.x*q[8+2*i] + f.y*q[8+2*i+1];
    }
    return acc;
}

// ---------------- prep ----------------
__global__ void k_prep(const float* __restrict__ Wk, const float* __restrict__ Wv,
                       const float* __restrict__ W_ih, const float* __restrict__ W_hh,
                       const float* __restrict__ W1, const float* __restrict__ W2,
                       const float* __restrict__ Wq) {
    int i = blockIdx.x * 256 + threadIdx.x;
    if (i < 1024) {
        int d4 = i >> 6, c = i & 63;
        float4 fk = *(const float4*)(Wk + c*64 + d4*4);
        float4 fv = *(const float4*)(Wv + c*64 + d4*4);
        ulonglong2 k2, v2;
        k2.x = packf2(fk.x, fk.y); k2.y = packf2(fk.z, fk.w);
        v2.x = packf2(fv.x, fv.y); v2.y = packf2(fv.z, fv.w);
        g_wk2v[i] = k2;
        g_wv2v[i] = v2;
    }
    if (i < 4096) {
        int d = i >> 6, x = i & 63;
        g_WgA[i] = make_float4(W_ih[x*64 + d], W_ih[(64+x)*64 + d],
                               W_ih[(128+x)*64 + d], W_hh[x*64 + d]);
        g_WgB[i] = make_float2(W_hh[(64+x)*64 + d], W_hh[(128+x)*64 + d]);
        g_W1p[i] = make_float2(W1[(2*x)*64 + d], W1[(2*x+1)*64 + d]);
        g_W2p[i] = make_float2(W2[x*128 + 2*d], W2[x*128 + 2*d + 1]);
    }
    if (i < 2048) {
        int d2 = i >> 6, dd = i & 63;
        g_Wqp[i] = make_float2(Wq[dd*64 + 2*d2], Wq[dd*64 + 2*d2 + 1]);
    }
}

// ---------------- K1: mask-compact + LN + k/v GEMM (no reg spills) ----------------
__global__ __launch_bounds__(256)
void k_ln_kv(const float* __restrict__ inputs, const int* __restrict__ mask,
             const float* __restrict__ bk, const float* __restrict__ bv,
             const float* __restrict__ lnw, const float* __restrict__ lnb) {
    __shared__ __align__(16) float xs[TILE_R*64];
    __shared__ int tpos[TILE_R];
    __shared__ int cmap[TILE_R];
    __shared__ int wc[2];

    int tid = threadIdx.x;
    int lane = tid & 31, warp = tid >> 5;
    size_t row0 = (size_t)blockIdx.x * TILE_R;

    if (tid < 64) {
        int mm = mask[row0 + tid] != 0;
        unsigned bal = __ballot_sync(~0u, mm);
        if (lane == 0) wc[warp] = __popc(bal);
        tpos[tid] = mm ? __popc(bal & ((1u << lane) - 1u)) : -1;
    }
    __syncthreads();
    int act = wc[0] + wc[1];
    if (tid < 64 && tpos[tid] >= 0)
        cmap[tpos[tid] + (tid >= 32 ? wc[0] : 0)] = tid;
    if (tid == 0) g_cnt[blockIdx.x] = act;
    __syncthreads();

    {
        float lw0 = lnw[lane], lw1 = lnw[lane+32];
        float lb0 = lnb[lane], lb1 = lnb[lane+32];
        for (int ci = warp; ci < act; ci += 8) {
            int r = cmap[ci];
            const float* src = inputs + (row0 + r)*64;
            float v0 = src[lane], v1 = src[lane+32];
            float s = v0 + v1;
            #pragma unroll
            for (int o = 16; o; o >>= 1) s += __shfl_xor_sync(~0u, s, o);
            float mu = s * (1.f/64.f);
            float d0 = v0 - mu, d1 = v1 - mu;
            float q = d0*d0 + d1*d1;
            #pragma unroll
            for (int o = 16; o; o >>= 1) q += __shfl_xor_sync(~0u, q, o);
            float rs = rsqrtf(q * (1.f/64.f) + LN_EPS);
            xs[ci*64 + lane]      = d0*rs*lw0 + lb0;
            xs[ci*64 + 32 + lane] = d1*rs*lw1 + lb1;
        }
    }
    __syncthreads();

    // GEMM over compacted rows: 16 rows per group, 4 rows per thread (low reg pressure)
    int c  = tid & 63;
    int rb = tid >> 6;
    float bkc = bk[c], bvc = bv[c];
    const ulonglong2* xs2 = reinterpret_cast<const ulonglong2*>(xs);
    int G = (act + 15) >> 4;
    for (int g = 0; g < G; ++g) {
        ull ak[4], av[4];
        #pragma unroll
        for (int t = 0; t < 4; ++t) { ak[t] = 0ull; av[t] = 0ull; }
        #pragma unroll
        for (int d4 = 0; d4 < 16; ++d4) {
            ulonglong2 wk = __ldg(g_wk2v + d4*64 + c);
            ulonglong2 wv = __ldg(g_wv2v + d4*64 + c);
            #pragma unroll
            for (int t = 0; t < 4; ++t) {
                int ci = g*16 + rb + 4*t;
                ulonglong2 x = xs2[ci*16 + d4];
                ak[t] = ffma2(x.x, wk.x, ak[t]);
                ak[t] = ffma2(x.y, wk.y, ak[t]);
                av[t] = ffma2(x.x, wv.x, av[t]);
                av[t] = ffma2(x.y, wv.y, av[t]);
            }
        }
        #pragma unroll
        for (int t = 0; t < 4; ++t) {
            int ci = g*16 + rb + 4*t;
            if (ci < act) {
                float2 k2 = unpackf2(ak[t]);
                float2 v2 = unpackf2(av[t]);
                g_kh[(row0 + ci)*64 + c] = __float2half_rn(k2.x + k2.y + bkc);
                g_v [(row0 + ci)*64 + c] = v2.x + v2.y + bvc;
            }
        }
    }
    // rows [act, pad8) never written -> stay zero (bss), safe for padded attn loops
}

// ---------------- LN over slot rows ----------------
__device__ __forceinline__ void lnrows(const float* in, float* out,
                                       const float* __restrict__ w,
                                       const float* __restrict__ bia, int tid, int nrows) {
    int wp = tid >> 5, lane = tid & 31;
    if (wp >= nrows) return;
    const float* p = in + wp*64;
    float v0 = p[lane], v1 = p[lane+32];
    float s = v0 + v1;
    #pragma unroll
    for (int o = 16; o; o >>= 1) s += __shfl_xor_sync(~0u, s, o);
    float mu = s * (1.f/64.f);
    float d0 = v0 - mu, d1 = v1 - mu;
    float q = d0*d0 + d1*d1;
    #pragma unroll
    for (int o = 16; o; o >>= 1) q += __shfl_xor_sync(~0u, q, o);
    float rs = rsqrtf(q * (1.f/64.f) + LN_EPS);
    out[wp*64 + lane]      = d0*rs*w[lane] + bia[lane];
    out[wp*64 + lane + 32] = d1*rs*w[lane+32] + bia[lane+32];
}

// ---------------- init ----------------
__global__ __launch_bounds__(256)
void k_init(const float* __restrict__ noise, const float* __restrict__ mu,
            const float* __restrict__ sg,
            const float* __restrict__ ln_s_w, const float* __restrict__ ln_s_b,
            const float* __restrict__ bq) {
    __shared__ float sl[512], sn[512];
    int b = blockIdx.x, tid = threadIdx.x;
    #pragma unroll
    for (int u = 0; u < 2; ++u) {
        int t = tid + 256*u, dd = t & 63;
        float s = mu[dd] + sg[dd]*noise[b*512 + t];
        sl[t] = s;
        g_slots[b*512 + t] = s;
    }
    __syncthreads();
    lnrows(sl, sn, ln_s_w, ln_s_b, tid, 8);
    __syncthreads();
    #pragma unroll
    for (int u = 0; u < 2; ++u) {
        int t = tid + 256*u, j = t >> 6, dd = t & 63;
        float acc = bq[dd];
        const float2* sj2 = (const float2*)(sn + j*64);
        #pragma unroll 8
        for (int d2 = 0; d2 < 32; ++d2) {
            float2 w = g_Wqp[d2*64 + dd];
            float2 s2 = sj2[d2];
            acc += s2.x*w.x + s2.y*w.y;
        }
        g_q[b*512 + t] = acc * SCALE;
    }
}

// ---------------- attention: fp16 k (phase A) + fp32 v f32x2 (phase C) ----------------
__global__ __launch_bounds__(256)
void k_attn() {
    __shared__ float dots[8*DSTR];
    __shared__ float att[8*DSTR];
    __shared__ float redP[8*512];
    __shared__ float redS[64];
    __shared__ int   cnts[4];

    int b = blockIdx.y, chunk = blockIdx.x;
    int tid = threadIdx.x;
    int warp = tid >> 5, lane = tid & 31;
    int jj = lane & 7;
    int gg = lane >> 3;

    if (tid < 4) cnts[tid] = g_cnt[b*(N/TILE_R) + chunk*4 + tid];

    float q[16];
    {
        const float4* qp = (const float4*)(g_q + b*512 + jj*64) + (gg << 2);
        #pragma unroll
        for (int i = 0; i < 4; ++i) {
            float4 t4 = qp[i];
            q[4*i] = t4.x; q[4*i+1] = t4.y; q[4*i+2] = t4.z; q[4*i+3] = t4.w;
        }
    }
    __syncthreads();

    // Phase A: dots (fp16 k)
    #pragma unroll
    for (int s = 0; s < 4; ++s) {
        int nit = (cnts[s] + 7) >> 3;
        const __half* kb = g_kh + ((size_t)(b*(N/TILE_R) + chunk*4 + s) * TILE_R) * 64;
        #pragma unroll 2
        for (int it = 0; it < nit; ++it) {
            int r = it*8 + warp;
            const uint4* kp = (const uint4*)(kb + r*64) + gg*2;
            uint4 u0 = kp[0], u1 = kp[1];
            float d = doth16(u0, u1, q);
            d += __shfl_xor_sync(~0u, d, 8);
            d += __shfl_xor_sync(~0u, d, 16);
            if (gg == 0) dots[jj*DSTR + s*64 + r] = d;
        }
    }
    __syncthreads();

    // Phase B: in-thread softmax; zero att on pad rows
    {
        int s = tid >> 6, r = tid & 63;
        int act = cnts[s];
        int pad8 = (act + 7) & ~7;
        if (r < act) {
            float d[8];
            #pragma unroll
            for (int j = 0; j < 8; ++j) d[j] = dots[j*DSTR + tid];
            float m = d[0];
            #pragma unroll
            for (int j = 1; j < 8; ++j) m = fmaxf(m, d[j]);
            float e[8], sum = 0.f;
            #pragma unroll
            for (int j = 0; j < 8; ++j) { e[j] = __expf(d[j] - m); sum += e[j]; }
            float inv = __fdividef(1.f, sum);
            #pragma unroll
            for (int j = 0; j < 8; ++j) att[j*DSTR + tid] = e[j]*inv + EPSA;
        } else if (r < pad8) {
            #pragma unroll
            for (int j = 0; j < 8; ++j) att[j*DSTR + tid] = 0.f;
        }
    }
    __syncthreads();

    // Phase C: P accumulation (fp32 v, f32x2)
    ull P2[8];
    #pragma unroll
    for (int i = 0; i < 8; ++i) P2[i] = 0ull;
    float S = 0.f;
    #pragma unroll
    for (int s = 0; s < 4; ++s) {
        int nit = (cnts[s] + 7) >> 3;
        const float* vb = g_v + ((size_t)(b*(N/TILE_R) + chunk*4 + s) * TILE_R) * 64;
        #pragma unroll 2
        for (int it = 0; it < nit; ++it) {
            int r = it*8 + warp;
            float a = att[jj*DSTR + s*64 + r];
            S += a;
            ull a2 = packf2(a, a);
            const ulonglong2* vp = (const ulonglong2*)(vb + r*64) + (gg << 2);
            ulonglong2 x0 = vp[0], x1 = vp[1], x2 = vp[2], x3 = vp[3];
            P2[0] = ffma2(x0.x, a2, P2[0]); P2[1] = ffma2(x0.y, a2, P2[1]);
            P2[2] = ffma2(x1.x, a2, P2[2]); P2[3] = ffma2(x1.y, a2, P2[3]);
            P2[4] = ffma2(x2.x, a2, P2[4]); P2[5] = ffma2(x2.y, a2, P2[5]);
            P2[6] = ffma2(x3.x, a2, P2[6]); P2[7] = ffma2(x3.y, a2, P2[7]);
        }
    }

    float* rp = redP + warp*512 + jj*64 + (gg << 4);
    #pragma unroll
    for (int i = 0; i < 4; ++i) {
        float2 f0 = unpackf2(P2[2*i]), f1 = unpackf2(P2[2*i+1]);
        *(float4*)(rp + 4*i) = make_float4(f0.x, f0.y, f1.x, f1.y);
    }
    if (gg == 0) redS[warp*8 + jj] = S;
    __syncthreads();

    #pragma unroll
    for (int u = 0; u < 2; ++u) {
        int t = tid + 256*u;
        float s = 0.f;
        #pragma unroll
        for (int w = 0; w < 8; ++w) s += redP[w*512 + t];
        g_Pp[((size_t)b*NB + chunk)*512 + t] = s;
    }
    if (tid < 8) {
        float s = 0.f;
        #pragma unroll
        for (int w = 0; w < 8; ++w) s += redS[w*8 + tid];
        g_Sp[(b*NB + chunk)*8 + tid] = s;
    }
}

// ---------------- slot update: GRU + residual MLP (+ next q); 4 slots/block ----------------
__global__ __launch_bounds__(256)
void k_update(const float* __restrict__ b_ih, const float* __restrict__ b_hh,
              const float* __restrict__ b1, const float* __restrict__ b2,
              const float* __restrict__ ln_ff_w, const float* __restrict__ ln_ff_b,
              const float* __restrict__ ln_s_w, const float* __restrict__ ln_s_b,
              const float* __restrict__ bq,
              float* __restrict__ d_out, int last) {
    __shared__ float upd[256], prev[256], snew[256], ffs[256], hid[512], sfin[256], Ssm[4];
    int b = blockIdx.y, half = blockIdx.x, tid = threadIdx.x;
    int j0 = half * 4;
    int j = tid >> 6, dd = tid & 63;
    int J = j0 + j;

    if (tid < 4) {
        float s = 0.f;
        const float* sp = g_Sp + b*NB*8 + j0 + tid;
        #pragma unroll
        for (int p = 0; p < NB; ++p) s += sp[p*8];
        Ssm[tid] = s;
    }
    float pr;
    {
        float s = 0.f;
        const float* pp = g_Pp + (size_t)b*NB*512 + J*64 + dd;
        #pragma unroll
        for (int p = 0; p < NB; ++p) s += pp[p*512];
        pr = s;
        prev[tid] = g_slots[b*512 + J*64 + dd];
    }
    __syncthreads();
    upd[tid] = pr / Ssm[j];
    __syncthreads();

    // GRU with packed weights
    {
        const float* uj = upd + j*64;
        const float* hj = prev + j*64;
        float xr = b_ih[dd], xz = b_ih[64+dd], xn = b_ih[128+dd];
        float hr = b_hh[dd], hz = b_hh[64+dd], hn = b_hh[128+dd];
        #pragma unroll 8
        for (int d = 0; d < 64; ++d) {
            float uu = uj[d], hh = hj[d];
            float4 wa = __ldg(g_WgA + d*64 + dd);
            float2 wb = __ldg(g_WgB + d*64 + dd);
            xr += uu*wa.x; xz += uu*wa.y; xn += uu*wa.z;
            hr += hh*wa.w; hz += hh*wb.x; hn += hh*wb.y;
        }
        float rg = 1.f/(1.f + __expf(-(xr + hr)));
        float zg = 1.f/(1.f + __expf(-(xz + hz)));
        float t2 = __expf(2.f*(xn + rg*hn));
        float nn = 1.f - 2.f/(t2 + 1.f);
        snew[tid] = (1.f - zg)*nn + zg*prev[tid];
    }
    __syncthreads();
    lnrows(snew, ffs, ln_ff_w, ln_ff_b, tid, 4);
    __syncthreads();
    // MLP layer 1
    {
        int h2 = dd;
        float a0 = b1[2*h2], a1 = b1[2*h2+1];
        const float* fj = ffs + j*64;
        #pragma unroll 8
        for (int d = 0; d < 64; ++d) {
            float2 w = __ldg(g_W1p + d*64 + h2);
            float f = fj[d];
            a0 += f*w.x; a1 += f*w.y;
        }
        hid[j*128 + 2*h2]   = fmaxf(a0, 0.f);
        hid[j*128 + 2*h2+1] = fmaxf(a1, 0.f);
    }
    __syncthreads();
    {
        float acc = b2[dd];
        const float2* hj2 = (const float2*)(hid + j*128);
        #pragma unroll 8
        for (int h2 = 0; h2 < 64; ++h2) {
            float2 w = __ldg(g_W2p + h2*64 + dd);
            float2 hv = hj2[h2];
            acc += hv.x*w.x + hv.y*w.y;
        }
        float o = snew[tid] + acc;
        sfin[tid] = o;
        g_slots[b*512 + J*64 + dd] = o;
        if (last) d_out[b*512 + J*64 + dd] = o;
    }
    if (!last) {
        __syncthreads();
        lnrows(sfin, ffs, ln_s_w, ln_s_b, tid, 4);
        __syncthreads();
        {
            float acc = bq[dd];
            const float2* sj2 = (const float2*)(ffs + j*64);
            #pragma unroll 8
            for (int d2 = 0; d2 < 32; ++d2) {
                float2 w = __ldg(g_Wqp + d2*64 + dd);
                float2 s2 = sj2[d2];
                acc += s2.x*w.x + s2.y*w.y;
            }
            g_q[b*512 + J*64 + dd] = acc * SCALE;
        }
    }
}

// ---------------- launch ----------------
extern "C" void kernel_launch(void* const* d_in, const int* in_sizes, int n_in,
                              void* d_out, int out_size) {
    const float* inputs     = (const float*)d_in[0];
    const int*   mask       = (const int*)  d_in[1];
    const float* noise      = (const float*)d_in[2];
    const float* slots_mu   = (const float*)d_in[3];
    const float* slots_sig  = (const float*)d_in[4];
    const float* Wq         = (const float*)d_in[5];
    const float* bq         = (const float*)d_in[6];
    const float* Wk         = (const float*)d_in[7];
    const float* bk         = (const float*)d_in[8];
    const float* Wv         = (const float*)d_in[9];
    const float* bv         = (const float*)d_in[10];
    const float* W_ih       = (const float*)d_in[11];
    const float* b_ih       = (const float*)d_in[12];
    const float* W_hh       = (const float*)d_in[13];
    const float* b_hh       = (const float*)d_in[14];
    const float* W1         = (const float*)d_in[15];
    const float* b1         = (const float*)d_in[16];
    const float* W2         = (const float*)d_in[17];
    const float* b2         = (const float*)d_in[18];
    const float* ln_in_w    = (const float*)d_in[19];
    const float* ln_in_b    = (const float*)d_in[20];
    const float* ln_s_w     = (const float*)d_in[21];
    const float* ln_s_b     = (const float*)d_in[22];
    const float* ln_ff_w    = (const float*)d_in[23];
    const float* ln_ff_b    = (const float*)d_in[24];
    float* out = (float*)d_out;

    k_prep<<<48, 256>>>(Wk, Wv, W_ih, W_hh, W1, W2, Wq);
    k_ln_kv<<<(B*N)/TILE_R, 256>>>(inputs, mask, bk, bv, ln_in_w, ln_in_b);
    k_init<<<B, 256>>>(noise, slots_mu, slots_sig, ln_s_w, ln_s_b, bq);
    for (int it = 0; it < ITERS; ++it) {
        k_attn<<<dim3(NB, B), 256>>>();
        k_update<<<dim3(2, B), 256>>>(b_ih, b_hh, b1, b2, ln_ff_w, ln_ff_b,
                                      ln_s_w, ln_s_b, bq, out, it == ITERS-1 ? 1 : 0);
    }
}

// round 10
// speedup vs baseline: 1.3330x; 1.3330x over previous
#include <cuda_runtime.h>
#include <cuda_fp16.h>
#include <cstdint>

// ---------------- problem constants ----------------
#define B       64
#define N       4096
#define D       64
#define H       128
#define NS      8
#define ITERS   3
#define EPSA    1e-8f
#define LN_EPS  1e-5f
#define SCALE   0.125f

#define TILE_R  64              // rows per region in kv kernel
#define NB      16              // chunks per batch in attention (256 rows each)
#define DSTR    257             // padded stride for dots/att smem

typedef unsigned long long ull;

// ---------------- device scratch ----------------
__device__ __half g_kh[B*N*D];         // compacted per 64-row region, fp16
__device__ __half g_vh[B*N*D];
__device__ int    g_cnt[B*N/TILE_R];   // active rows per region
__device__ float  g_slots[B*NS*D];
__device__ float  g_q[B*NS*D];
__device__ float  g_Pp[B*NB*NS*D];
__device__ float  g_Sp[B*NB*NS];
__device__ ulonglong2 g_wk2v[16*64];   // [d4][c] packed f32x2 pairs
__device__ ulonglong2 g_wv2v[16*64];
__device__ float4 g_WgA[64*64];        // [d][dd] = (Wih_r, Wih_z, Wih_n, Whh_r)
__device__ float2 g_WgB[64*64];        // [d][dd] = (Whh_z, Whh_n)
__device__ float2 g_W1p[64*64];        // [d][h2]
__device__ float2 g_W2p[64*64];        // [h2][dd]
__device__ float2 g_Wqp[32*64];        // [d2][dd]

// ---------------- f32x2 helpers ----------------
__device__ __forceinline__ ull packf2(float x, float y) {
    ull r;
    asm("mov.b64 %0, {%1,%2};" : "=l"(r) : "f"(x), "f"(y));
    return r;
}
__device__ __forceinline__ float2 unpackf2(ull v) {
    float2 f;
    asm("mov.b64 {%0,%1}, %2;" : "=f"(f.x), "=f"(f.y) : "l"(v));
    return f;
}
__device__ __forceinline__ ull ffma2(ull a, ull b, ull c) {
    ull d;
    asm("fma.rn.f32x2 %0, %1, %2, %3;" : "=l"(d) : "l"(a), "l"(b), "l"(c));
    return d;
}
// convert one half2 to packed f32x2 operand
__device__ __forceinline__ ull h2f2(__half2 h) {
    float2 f = __half22float2(h);
    return packf2(f.x, f.y);
}

// dot of 16 halves (two uint4) against prepacked q2[0..7], via f32x2
__device__ __forceinline__ float doth16x2(uint4 u0, uint4 u1, const ull* q2) {
    const __half2* h0 = reinterpret_cast<const __half2*>(&u0);
    const __half2* h1 = reinterpret_cast<const __half2*>(&u1);
    ull acc = 0ull;
    #pragma unroll
    for (int i = 0; i < 4; ++i) acc = ffma2(h2f2(h0[i]), q2[i], acc);
    #pragma unroll
    for (int i = 0; i < 4; ++i) acc = ffma2(h2f2(h1[i]), q2[4+i], acc);
    float2 f = unpackf2(acc);
    return f.x + f.y;
}

// ---------------- prep ----------------
__global__ void k_prep(const float* __restrict__ Wk, const float* __restrict__ Wv,
                       const float* __restrict__ W_ih, const float* __restrict__ W_hh,
                       const float* __restrict__ W1, const float* __restrict__ W2,
                       const float* __restrict__ Wq) {
    int i = blockIdx.x * 256 + threadIdx.x;
    if (i < 1024) {
        int d4 = i >> 6, c = i & 63;
        float4 fk = *(const float4*)(Wk + c*64 + d4*4);
        float4 fv = *(const float4*)(Wv + c*64 + d4*4);
        ulonglong2 k2, v2;
        k2.x = packf2(fk.x, fk.y); k2.y = packf2(fk.z, fk.w);
        v2.x = packf2(fv.x, fv.y); v2.y = packf2(fv.z, fv.w);
        g_wk2v[i] = k2;
        g_wv2v[i] = v2;
    }
    if (i < 4096) {
        int d = i >> 6, x = i & 63;
        g_WgA[i] = make_float4(W_ih[x*64 + d], W_ih[(64+x)*64 + d],
                               W_ih[(128+x)*64 + d], W_hh[x*64 + d]);
        g_WgB[i] = make_float2(W_hh[(64+x)*64 + d], W_hh[(128+x)*64 + d]);
        g_W1p[i] = make_float2(W1[(2*x)*64 + d], W1[(2*x+1)*64 + d]);
        g_W2p[i] = make_float2(W2[x*128 + 2*d], W2[x*128 + 2*d + 1]);
    }
    if (i < 2048) {
        int d2 = i >> 6, dd = i & 63;
        g_Wqp[i] = make_float2(Wq[dd*64 + 2*d2], Wq[dd*64 + 2*d2 + 1]);
    }
}

// ---------------- K1: mask-compact + LN + k/v GEMM (R5 shape) ----------------
__global__ __launch_bounds__(256, 4)
void k_ln_kv(const float* __restrict__ inputs, const int* __restrict__ mask,
             const float* __restrict__ bk, const float* __restrict__ bv,
             const float* __restrict__ lnw, const float* __restrict__ lnb) {
    __shared__ __align__(16) float xs[TILE_R*64];
    __shared__ int tpos[TILE_R];
    __shared__ int cmap[TILE_R];
    __shared__ int wc[2];

    int tid = threadIdx.x;
    int lane = tid & 31, warp = tid >> 5;
    size_t row0 = (size_t)blockIdx.x * TILE_R;

    if (tid < 64) {
        int mm = mask[row0 + tid] != 0;
        unsigned bal = __ballot_sync(~0u, mm);
        if (lane == 0) wc[warp] = __popc(bal);
        tpos[tid] = mm ? __popc(bal & ((1u << lane) - 1u)) : -1;
    }
    __syncthreads();
    int act = wc[0] + wc[1];
    if (tid < 64 && tpos[tid] >= 0)
        cmap[tpos[tid] + (tid >= 32 ? wc[0] : 0)] = tid;
    if (tid == 0) g_cnt[blockIdx.x] = act;
    __syncthreads();

    {
        float lw0 = lnw[lane], lw1 = lnw[lane+32];
        float lb0 = lnb[lane], lb1 = lnb[lane+32];
        for (int ci = warp; ci < act; ci += 8) {
            int r = cmap[ci];
            const float* src = inputs + (row0 + r)*64;
            float v0 = src[lane], v1 = src[lane+32];
            float s = v0 + v1;
            #pragma unroll
            for (int o = 16; o; o >>= 1) s += __shfl_xor_sync(~0u, s, o);
            float mu = s * (1.f/64.f);
            float d0 = v0 - mu, d1 = v1 - mu;
            float q = d0*d0 + d1*d1;
            #pragma unroll
            for (int o = 16; o; o >>= 1) q += __shfl_xor_sync(~0u, q, o);
            float rs = rsqrtf(q * (1.f/64.f) + LN_EPS);
            xs[ci*64 + lane]      = d0*rs*lw0 + lb0;
            xs[ci*64 + 32 + lane] = d1*rs*lw1 + lb1;
        }
    }
    __syncthreads();

    int c  = tid & 63;
    int rb = tid >> 6;
    float bkc = bk[c], bvc = bv[c];
    const ulonglong2* xs2 = reinterpret_cast<const ulonglong2*>(xs);
    int G = (act + 31) >> 5;
    for (int g = 0; g < G; ++g) {
        ull ak[8], av[8];
        #pragma unroll
        for (int t = 0; t < 8; ++t) { ak[t] = 0ull; av[t] = 0ull; }
        #pragma unroll
        for (int d4 = 0; d4 < 16; ++d4) {
            ulonglong2 wk = __ldg(g_wk2v + d4*64 + c);
            ulonglong2 wv = __ldg(g_wv2v + d4*64 + c);
            #pragma unroll
            for (int t = 0; t < 8; ++t) {
                int ci = g*32 + rb + 4*t;
                ulonglong2 x = xs2[ci*16 + d4];
                ak[t] = ffma2(x.x, wk.x, ak[t]);
                ak[t] = ffma2(x.y, wk.y, ak[t]);
                av[t] = ffma2(x.x, wv.x, av[t]);
                av[t] = ffma2(x.y, wv.y, av[t]);
            }
        }
        #pragma unroll
        for (int t = 0; t < 8; ++t) {
            int ci = g*32 + rb + 4*t;
            if (ci < act) {
                float2 k2 = unpackf2(ak[t]);
                float2 v2 = unpackf2(av[t]);
                g_kh[(row0 + ci)*64 + c] = __float2half_rn(k2.x + k2.y + bkc);
                g_vh[(row0 + ci)*64 + c] = __float2half_rn(v2.x + v2.y + bvc);
            }
        }
    }
    // rows [act, pad8) never written -> stay zero (bss), safe for padded attn loops
}

// ---------------- LN over slot rows ----------------
__device__ __forceinline__ void lnrows(const float* in, float* out,
                                       const float* __restrict__ w,
                                       const float* __restrict__ bia, int tid, int nrows) {
    int wp = tid >> 5, lane = tid & 31;
    if (wp >= nrows) return;
    const float* p = in + wp*64;
    float v0 = p[lane], v1 = p[lane+32];
    float s = v0 + v1;
    #pragma unroll
    for (int o = 16; o; o >>= 1) s += __shfl_xor_sync(~0u, s, o);
    float mu = s * (1.f/64.f);
    float d0 = v0 - mu, d1 = v1 - mu;
    float q = d0*d0 + d1*d1;
    #pragma unroll
    for (int o = 16; o; o >>= 1) q += __shfl_xor_sync(~0u, q, o);
    float rs = rsqrtf(q * (1.f/64.f) + LN_EPS);
    out[wp*64 + lane]      = d0*rs*w[lane] + bia[lane];
    out[wp*64 + lane + 32] = d1*rs*w[lane+32] + bia[lane+32];
}

// ---------------- init ----------------
__global__ __launch_bounds__(256)
void k_init(const float* __restrict__ noise, const float* __restrict__ mu,
            const float* __restrict__ sg,
            const float* __restrict__ ln_s_w, const float* __restrict__ ln_s_b,
            const float* __restrict__ bq) {
    __shared__ float sl[512], sn[512];
    int b = blockIdx.x, tid = threadIdx.x;
    #pragma unroll
    for (int u = 0; u < 2; ++u) {
        int t = tid + 256*u, dd = t & 63;
        float s = mu[dd] + sg[dd]*noise[b*512 + t];
        sl[t] = s;
        g_slots[b*512 + t] = s;
    }
    __syncthreads();
    lnrows(sl, sn, ln_s_w, ln_s_b, tid, 8);
    __syncthreads();
    #pragma unroll
    for (int u = 0; u < 2; ++u) {
        int t = tid + 256*u, j = t >> 6, dd = t & 63;
        float acc = bq[dd];
        const float2* sj2 = (const float2*)(sn + j*64);
        #pragma unroll 8
        for (int d2 = 0; d2 < 32; ++d2) {
            float2 w = g_Wqp[d2*64 + dd];
            float2 s2 = sj2[d2];
            acc += s2.x*w.x + s2.y*w.y;
        }
        g_q[b*512 + t] = acc * SCALE;
    }
}

// ---------------- attention: fp16 k/v storage + f32x2 accumulate ----------------
__global__ __launch_bounds__(256)
void k_attn() {
    __shared__ float dots[8*DSTR];
    __shared__ float att[8*DSTR];
    __shared__ float redP[8*512];
    __shared__ float redS[64];
    __shared__ int   cnts[4];

    int b = blockIdx.y, chunk = blockIdx.x;
    int tid = threadIdx.x;
    int warp = tid >> 5, lane = tid & 31;
    int jj = lane & 7;
    int gg = lane >> 3;

    if (tid < 4) cnts[tid] = g_cnt[b*(N/TILE_R) + chunk*4 + tid];

    ull q2[8];
    {
        const float4* qp = (const float4*)(g_q + b*512 + jj*64) + (gg << 2);
        #pragma unroll
        for (int i = 0; i < 4; ++i) {
            float4 t4 = qp[i];
            q2[2*i]   = packf2(t4.x, t4.y);
            q2[2*i+1] = packf2(t4.z, t4.w);
        }
    }
    __syncthreads();

    // Phase A: dots (fp16 k, f32x2 accumulate)
    #pragma unroll
    for (int s = 0; s < 4; ++s) {
        int nit = (cnts[s] + 7) >> 3;
        const __half* kb = g_kh + ((size_t)(b*(N/TILE_R) + chunk*4 + s) * TILE_R) * 64;
        #pragma unroll 2
        for (int it = 0; it < nit; ++it) {
            int r = it*8 + warp;
            const uint4* kp = (const uint4*)(kb + r*64) + gg*2;
            uint4 u0 = kp[0], u1 = kp[1];
            float d = doth16x2(u0, u1, q2);
            d += __shfl_xor_sync(~0u, d, 8);
            d += __shfl_xor_sync(~0u, d, 16);
            if (gg == 0) dots[jj*DSTR + s*64 + r] = d;
        }
    }
    __syncthreads();

    // Phase B: in-thread softmax; zero att on pad rows
    {
        int s = tid >> 6, r = tid & 63;
        int act = cnts[s];
        int pad8 = (act + 7) & ~7;
        if (r < act) {
            float d[8];
            #pragma unroll
            for (int j = 0; j < 8; ++j) d[j] = dots[j*DSTR + tid];
            float m = d[0];
            #pragma unroll
            for (int j = 1; j < 8; ++j) m = fmaxf(m, d[j]);
            float e[8], sum = 0.f;
            #pragma unroll
            for (int j = 0; j < 8; ++j) { e[j] = __expf(d[j] - m); sum += e[j]; }
            float inv = __fdividef(1.f, sum);
            #pragma unroll
            for (int j = 0; j < 8; ++j) att[j*DSTR + tid] = e[j]*inv + EPSA;
        } else if (r < pad8) {
            #pragma unroll
            for (int j = 0; j < 8; ++j) att[j*DSTR + tid] = 0.f;
        }
    }
    __syncthreads();

    // Phase C: P accumulation (fp16 v, f32x2 accumulate)
    ull P2[8];
    #pragma unroll
    for (int i = 0; i < 8; ++i) P2[i] = 0ull;
    float S = 0.f;
    #pragma unroll
    for (int s = 0; s < 4; ++s) {
        int nit = (cnts[s] + 7) >> 3;
        const __half* vb = g_vh + ((size_t)(b*(N/TILE_R) + chunk*4 + s) * TILE_R) * 64;
        #pragma unroll 2
        for (int it = 0; it < nit; ++it) {
            int r = it*8 + warp;
            float a = att[jj*DSTR + s*64 + r];
            S += a;
            ull a2 = packf2(a, a);
            const uint4* vp = (const uint4*)(vb + r*64) + gg*2;
            uint4 u0 = vp[0], u1 = vp[1];
            const __half2* h0 = reinterpret_cast<const __half2*>(&u0);
            const __half2* h1 = reinterpret_cast<const __half2*>(&u1);
            #pragma unroll
            for (int i = 0; i < 4; ++i) P2[i]   = ffma2(h2f2(h0[i]), a2, P2[i]);
            #pragma unroll
            for (int i = 0; i < 4; ++i) P2[4+i] = ffma2(h2f2(h1[i]), a2, P2[4+i]);
        }
    }

    float* rp = redP + warp*512 + jj*64 + (gg << 4);
    #pragma unroll
    for (int i = 0; i < 4; ++i) {
        float2 f0 = unpackf2(P2[2*i]), f1 = unpackf2(P2[2*i+1]);
        *(float4*)(rp + 4*i) = make_float4(f0.x, f0.y, f1.x, f1.y);
    }
    if (gg == 0) redS[warp*8 + jj] = S;
    __syncthreads();

    #pragma unroll
    for (int u = 0; u < 2; ++u) {
        int t = tid + 256*u;
        float s = 0.f;
        #pragma unroll
        for (int w = 0; w < 8; ++w) s += redP[w*512 + t];
        g_Pp[((size_t)b*NB + chunk)*512 + t] = s;
    }
    if (tid < 8) {
        float s = 0.f;
        #pragma unroll
        for (int w = 0; w < 8; ++w) s += redS[w*8 + tid];
        g_Sp[(b*NB + chunk)*8 + tid] = s;
    }
}

// ---------------- slot update: GRU + residual MLP (+ next q); 4 slots/block ----------------
__global__ __launch_bounds__(256)
void k_update(const float* __restrict__ b_ih, const float* __restrict__ b_hh,
              const float* __restrict__ b1, const float* __restrict__ b2,
              const float* __restrict__ ln_ff_w, const float* __restrict__ ln_ff_b,
              const float* __restrict__ ln_s_w, const float* __restrict__ ln_s_b,
              const float* __restrict__ bq,
              float* __restrict__ d_out, int last) {
    __shared__ float upd[256], prev[256], snew[256], ffs[256], hid[512], sfin[256], Ssm[4];
    int b = blockIdx.y, half = blockIdx.x, tid = threadIdx.x;
    int j0 = half * 4;
    int j = tid >> 6, dd = tid & 63;
    int J = j0 + j;

    if (tid < 4) {
        float s = 0.f;
        const float* sp = g_Sp + b*NB*8 + j0 + tid;
        #pragma unroll
        for (int p = 0; p < NB; ++p) s += sp[p*8];
        Ssm[tid] = s;
    }
    float pr;
    {
        float s = 0.f;
        const float* pp = g_Pp + (size_t)b*NB*512 + J*64 + dd;
        #pragma unroll
        for (int p = 0; p < NB; ++p) s += pp[p*512];
        pr = s;
        prev[tid] = g_slots[b*512 + J*64 + dd];
    }
    __syncthreads();
    upd[tid] = pr / Ssm[j];
    __syncthreads();

    // GRU with packed weights
    {
        const float* uj = upd + j*64;
        const float* hj = prev + j*64;
        float xr = b_ih[dd], xz = b_ih[64+dd], xn = b_ih[128+dd];
        float hr = b_hh[dd], hz = b_hh[64+dd], hn = b_hh[128+dd];
        #pragma unroll 8
        for (int d = 0; d < 64; ++d) {
            float uu = uj[d], hh = hj[d];
            float4 wa = __ldg(g_WgA + d*64 + dd);
            float2 wb = __ldg(g_WgB + d*64 + dd);
            xr += uu*wa.x; xz += uu*wa.y; xn += uu*wa.z;
            hr += hh*wa.w; hz += hh*wb.x; hn += hh*wb.y;
        }
        float rg = 1.f/(1.f + __expf(-(xr + hr)));
        float zg = 1.f/(1.f + __expf(-(xz + hz)));
        float t2 = __expf(2.f*(xn + rg*hn));
        float nn = 1.f - 2.f/(t2 + 1.f);
        snew[tid] = (1.f - zg)*nn + zg*prev[tid];
    }
    __syncthreads();
    lnrows(snew, ffs, ln_ff_w, ln_ff_b, tid, 4);
    __syncthreads();
    // MLP layer 1
    {
        int h2 = dd;
        float a0 = b1[2*h2], a1 = b1[2*h2+1];
        const float* fj = ffs + j*64;
        #pragma unroll 8
        for (int d = 0; d < 64; ++d) {
            float2 w = __ldg(g_W1p + d*64 + h2);
            float f = fj[d];
            a0 += f*w.x; a1 += f*w.y;
        }
        hid[j*128 + 2*h2]   = fmaxf(a0, 0.f);
        hid[j*128 + 2*h2+1] = fmaxf(a1, 0.f);
    }
    __syncthreads();
    {
        float acc = b2[dd];
        const float2* hj2 = (const float2*)(hid + j*128);
        #pragma unroll 8
        for (int h2 = 0; h2 < 64; ++h2) {
            float2 w = __ldg(g_W2p + h2*64 + dd);
            float2 hv = hj2[h2];
            acc += hv.x*w.x + hv.y*w.y;
        }
        float o = snew[tid] + acc;
        sfin[tid] = o;
        g_slots[b*512 + J*64 + dd] = o;
        if (last) d_out[b*512 + J*64 + dd] = o;
    }
    if (!last) {
        __syncthreads();
        lnrows(sfin, ffs, ln_s_w, ln_s_b, tid, 4);
        __syncthreads();
        {
            float acc = bq[dd];
            const float2* sj2 = (const float2*)(ffs + j*64);
            #pragma unroll 8
            for (int d2 = 0; d2 < 32; ++d2) {
                float2 w = __ldg(g_Wqp + d2*64 + dd);
                float2 s2 = sj2[d2];
                acc += s2.x*w.x + s2.y*w.y;
            }
            g_q[b*512 + J*64 + dd] = acc * SCALE;
        }
    }
}

// ---------------- launch ----------------
extern "C" void kernel_launch(void* const* d_in, const int* in_sizes, int n_in,
                              void* d_out, int out_size) {
    const float* inputs     = (const float*)d_in[0];
    const int*   mask       = (const int*)  d_in[1];
    const float* noise      = (const float*)d_in[2];
    const float* slots_mu   = (const float*)d_in[3];
    const float* slots_sig  = (const float*)d_in[4];
    const float* Wq         = (const float*)d_in[5];
    const float* bq         = (const float*)d_in[6];
    const float* Wk         = (const float*)d_in[7];
    const float* bk         = (const float*)d_in[8];
    const float* Wv         = (const float*)d_in[9];
    const float* bv         = (const float*)d_in[10];
    const float* W_ih       = (const float*)d_in[11];
    const float* b_ih       = (const float*)d_in[12];
    const float* W_hh       = (const float*)d_in[13];
    const float* b_hh       = (const float*)d_in[14];
    const float* W1         = (const float*)d_in[15];
    const float* b1         = (const float*)d_in[16];
    const float* W2         = (const float*)d_in[17];
    const float* b2         = (const float*)d_in[18];
    const float* ln_in_w    = (const float*)d_in[19];
    const float* ln_in_b    = (const float*)d_in[20];
    const float* ln_s_w     = (const float*)d_in[21];
    const float* ln_s_b     = (const float*)d_in[22];
    const float* ln_ff_w    = (const float*)d_in[23];
    const float* ln_ff_b    = (const float*)d_in[24];
    float* out = (float*)d_out;

    k_prep<<<48, 256>>>(Wk, Wv, W_ih, W_hh, W1, W2, Wq);
    k_ln_kv<<<(B*N)/TILE_R, 256>>>(inputs, mask, bk, bv, ln_in_w, ln_in_b);
    k_init<<<B, 256>>>(noise, slots_mu, slots_sig, ln_s_w, ln_s_b, bq);
    for (int it = 0; it < ITERS; ++it) {
        k_attn<<<dim3(NB, B), 256>>>();
        k_update<<<dim3(2, B), 256>>>(b_ih, b_hh, b1, b2, ln_ff_w, ln_ff_b,
                                      ln_s_w, ln_s_b, bq, out, it == ITERS-1 ? 1 : 0);
    }
}

// round 11
// speedup vs baseline: 1.4185x; 1.0641x over previous
#include <cuda_runtime.h>
#include <cuda_fp16.h>
#include <cstdint>

// ---------------- problem constants ----------------
#define B       64
#define N       4096
#define D       64
#define H       128
#define NS      8
#define ITERS   3
#define EPSA    1e-8f
#define LN_EPS  1e-5f
#define SCALE   0.125f

#define TILE_R  64              // rows per region in kv kernel
#define NB      16              // chunks per batch in attention (256 rows each)
#define DSTR    257             // padded stride for dots/att smem

typedef unsigned long long ull;

// ---------------- device scratch ----------------
__device__ __half g_kh[B*N*D];         // compacted per 64-row region, fp16
__device__ __half g_vh[B*N*D];
__device__ int    g_cnt[B*N/TILE_R];   // active rows per region
__device__ float  g_slots[B*NS*D];
__device__ float  g_q[B*NS*D];
__device__ float  g_Pp[B*NB*NS*D];
__device__ float  g_Sp[B*NB*NS];
__device__ ulonglong2 g_wk2v[16*64];   // [d4][c] packed f32x2 pairs
__device__ ulonglong2 g_wv2v[16*64];
__device__ float4 g_WgA[64*64];        // [d][dd] = (Wih_r, Wih_z, Wih_n, Whh_r)
__device__ float2 g_WgB[64*64];        // [d][dd] = (Whh_z, Whh_n)
__device__ float2 g_W1p[64*64];        // [d][h2]
__device__ float2 g_W2p[64*64];        // [h2][dd]
__device__ float2 g_Wqp[32*64];        // [d2][dd]

// ---------------- f32x2 helpers ----------------
__device__ __forceinline__ ull packf2(float x, float y) {
    ull r;
    asm("mov.b64 %0, {%1,%2};" : "=l"(r) : "f"(x), "f"(y));
    return r;
}
__device__ __forceinline__ float2 unpackf2(ull v) {
    float2 f;
    asm("mov.b64 {%0,%1}, %2;" : "=f"(f.x), "=f"(f.y) : "l"(v));
    return f;
}
__device__ __forceinline__ ull ffma2(ull a, ull b, ull c) {
    ull d;
    asm("fma.rn.f32x2 %0, %1, %2, %3;" : "=l"(d) : "l"(a), "l"(b), "l"(c));
    return d;
}

// dot of 16 halves (two uint4) against q[0..15] (scalar FFMA — R5 proven)
__device__ __forceinline__ float doth16(uint4 u0, uint4 u1, const float* q) {
    const __half2* h0 = reinterpret_cast<const __half2*>(&u0);
    const __half2* h1 = reinterpret_cast<const __half2*>(&u1);
    float acc = 0.f;
    #pragma unroll
    for (int i = 0; i < 4; ++i) {
        float2 f = __half22float2(h0[i]);
        acc += f.x*q[2*i] + f.y*q[2*i+1];
    }
    #pragma unroll
    for (int i = 0; i < 4; ++i) {
        float2 f = __half22float2(h1[i]);
        acc += f.x*q[8+2*i] + f.y*q[8+2*i+1];
    }
    return acc;
}

// ---------------- prep ----------------
__global__ void k_prep(const float* __restrict__ Wk, const float* __restrict__ Wv,
                       const float* __restrict__ W_ih, const float* __restrict__ W_hh,
                       const float* __restrict__ W1, const float* __restrict__ W2,
                       const float* __restrict__ Wq) {
    int i = blockIdx.x * 256 + threadIdx.x;
    if (i < 1024) {
        int d4 = i >> 6, c = i & 63;
        float4 fk = *(const float4*)(Wk + c*64 + d4*4);
        float4 fv = *(const float4*)(Wv + c*64 + d4*4);
        ulonglong2 k2, v2;
        k2.x = packf2(fk.x, fk.y); k2.y = packf2(fk.z, fk.w);
        v2.x = packf2(fv.x, fv.y); v2.y = packf2(fv.z, fv.w);
        g_wk2v[i] = k2;
        g_wv2v[i] = v2;
    }
    if (i < 4096) {
        int d = i >> 6, x = i & 63;
        g_WgA[i] = make_float4(W_ih[x*64 + d], W_ih[(64+x)*64 + d],
                               W_ih[(128+x)*64 + d], W_hh[x*64 + d]);
        g_WgB[i] = make_float2(W_hh[(64+x)*64 + d], W_hh[(128+x)*64 + d]);
        g_W1p[i] = make_float2(W1[(2*x)*64 + d], W1[(2*x+1)*64 + d]);
        g_W2p[i] = make_float2(W2[x*128 + 2*d], W2[x*128 + 2*d + 1]);
    }
    if (i < 2048) {
        int d2 = i >> 6, dd = i & 63;
        g_Wqp[i] = make_float2(Wq[dd*64 + 2*d2], Wq[dd*64 + 2*d2 + 1]);
    }
}

// ---------------- K1: mask-compact + shuffle-free LN + k/v GEMM ----------------
__global__ __launch_bounds__(256, 4)
void k_ln_kv(const float* __restrict__ inputs, const int* __restrict__ mask,
             const float* __restrict__ bk, const float* __restrict__ bv,
             const float* __restrict__ lnw, const float* __restrict__ lnb) {
    __shared__ __align__(16) float xs[TILE_R*64];
    __shared__ float ps[TILE_R*4], pq[TILE_R*4];
    __shared__ float rmu[TILE_R], rrs[TILE_R];
    __shared__ int tpos[TILE_R];
    __shared__ int cmap[TILE_R];
    __shared__ int wc[2];

    int tid = threadIdx.x;
    int lane = tid & 31, warp = tid >> 5;
    size_t row0 = (size_t)blockIdx.x * TILE_R;

    if (tid < 64) {
        int mm = mask[row0 + tid] != 0;
        unsigned bal = __ballot_sync(~0u, mm);
        if (lane == 0) wc[warp] = __popc(bal);
        tpos[tid] = mm ? __popc(bal & ((1u << lane) - 1u)) : -1;
    }
    __syncthreads();
    int act = wc[0] + wc[1];
    if (tid < 64 && tpos[tid] >= 0)
        cmap[tpos[tid] + (tid >= 32 ? wc[0] : 0)] = tid;
    if (tid == 0) g_cnt[blockIdx.x] = act;
    __syncthreads();

    // LN-a: gather active rows coalesced (16 threads per row)
    {
        int rph = tid >> 4;       // 0..15
        int quad = tid & 15;      // float4 index within row
        for (int base = 0; base < act; base += 16) {
            int ci = base + rph;
            if (ci < act) {
                int r = cmap[ci];
                *(float4*)(xs + ci*64 + quad*4) =
                    *(const float4*)(inputs + (row0 + r)*64 + quad*4);
            }
        }
    }
    __syncthreads();

    // LN-b: per-(row, quarter) partial sum / sumsq (no shuffles)
    {
        int ci = tid >> 2, q = tid & 3;
        if (ci < act) {
            const float4* p = (const float4*)(xs + ci*64 + q*16);
            float s = 0.f, ss = 0.f;
            #pragma unroll
            for (int i = 0; i < 4; ++i) {
                float4 v = p[i];
                s  += (v.x + v.y) + (v.z + v.w);
                ss += (v.x*v.x + v.y*v.y) + (v.z*v.z + v.w*v.w);
            }
            ps[ci*4 + q] = s;
            pq[ci*4 + q] = ss;
        }
    }
    __syncthreads();

    // LN-c: combine 4 partials per row
    if (tid < act) {
        float s  = (ps[tid*4] + ps[tid*4+1]) + (ps[tid*4+2] + ps[tid*4+3]);
        float ss = (pq[tid*4] + pq[tid*4+1]) + (pq[tid*4+2] + pq[tid*4+3]);
        float mu  = s * (1.f/64.f);
        float var = ss * (1.f/64.f) - mu*mu;
        rmu[tid] = mu;
        rrs[tid] = rsqrtf(var + LN_EPS);
    }
    __syncthreads();

    // LN-d: normalize in place (256 threads over act*16 float4s)
    {
        int tot = act * 16;
        for (int e = tid; e < tot; e += 256) {
            int ci = e >> 4, q = e & 15;
            float4 v = *(float4*)(xs + ci*64 + q*4);
            float mu = rmu[ci], rs = rrs[ci];
            float4 w4 = __ldg((const float4*)lnw + q);
            float4 b4 = __ldg((const float4*)lnb + q);
            v.x = (v.x - mu)*rs*w4.x + b4.x;
            v.y = (v.y - mu)*rs*w4.y + b4.y;
            v.z = (v.z - mu)*rs*w4.z + b4.z;
            v.w = (v.w - mu)*rs*w4.w + b4.w;
            *(float4*)(xs + ci*64 + q*4) = v;
        }
    }
    __syncthreads();

    // GEMM over compacted rows: 32 rows per group, 8 rows per thread (R5 shape)
    int c  = tid & 63;
    int rb = tid >> 6;
    float bkc = bk[c], bvc = bv[c];
    const ulonglong2* xs2 = reinterpret_cast<const ulonglong2*>(xs);
    int G = (act + 31) >> 5;
    for (int g = 0; g < G; ++g) {
        ull ak[8], av[8];
        #pragma unroll
        for (int t = 0; t < 8; ++t) { ak[t] = 0ull; av[t] = 0ull; }
        #pragma unroll
        for (int d4 = 0; d4 < 16; ++d4) {
            ulonglong2 wk = __ldg(g_wk2v + d4*64 + c);
            ulonglong2 wv = __ldg(g_wv2v + d4*64 + c);
            #pragma unroll
            for (int t = 0; t < 8; ++t) {
                int ci = g*32 + rb + 4*t;
                ulonglong2 x = xs2[ci*16 + d4];
                ak[t] = ffma2(x.x, wk.x, ak[t]);
                ak[t] = ffma2(x.y, wk.y, ak[t]);
                av[t] = ffma2(x.x, wv.x, av[t]);
                av[t] = ffma2(x.y, wv.y, av[t]);
            }
        }
        #pragma unroll
        for (int t = 0; t < 8; ++t) {
            int ci = g*32 + rb + 4*t;
            if (ci < act) {
                float2 k2 = unpackf2(ak[t]);
                float2 v2 = unpackf2(av[t]);
                g_kh[(row0 + ci)*64 + c] = __float2half_rn(k2.x + k2.y + bkc);
                g_vh[(row0 + ci)*64 + c] = __float2half_rn(v2.x + v2.y + bvc);
            }
        }
    }
    // rows [act, pad8) never written -> stay zero (bss), safe for padded attn loops
}

// ---------------- LN over slot rows ----------------
__device__ __forceinline__ void lnrows(const float* in, float* out,
                                       const float* __restrict__ w,
                                       const float* __restrict__ bia, int tid, int nrows) {
    int wp = tid >> 5, lane = tid & 31;
    if (wp >= nrows) return;
    const float* p = in + wp*64;
    float v0 = p[lane], v1 = p[lane+32];
    float s = v0 + v1;
    #pragma unroll
    for (int o = 16; o; o >>= 1) s += __shfl_xor_sync(~0u, s, o);
    float mu = s * (1.f/64.f);
    float d0 = v0 - mu, d1 = v1 - mu;
    float q = d0*d0 + d1*d1;
    #pragma unroll
    for (int o = 16; o; o >>= 1) q += __shfl_xor_sync(~0u, q, o);
    float rs = rsqrtf(q * (1.f/64.f) + LN_EPS);
    out[wp*64 + lane]      = d0*rs*w[lane] + bia[lane];
    out[wp*64 + lane + 32] = d1*rs*w[lane+32] + bia[lane+32];
}

// ---------------- init ----------------
__global__ __launch_bounds__(256)
void k_init(const float* __restrict__ noise, const float* __restrict__ mu,
            const float* __restrict__ sg,
            const float* __restrict__ ln_s_w, const float* __restrict__ ln_s_b,
            const float* __restrict__ bq) {
    __shared__ float sl[512], sn[512];
    int b = blockIdx.x, tid = threadIdx.x;
    #pragma unroll
    for (int u = 0; u < 2; ++u) {
        int t = tid + 256*u, dd = t & 63;
        float s = mu[dd] + sg[dd]*noise[b*512 + t];
        sl[t] = s;
        g_slots[b*512 + t] = s;
    }
    __syncthreads();
    lnrows(sl, sn, ln_s_w, ln_s_b, tid, 8);
    __syncthreads();
    #pragma unroll
    for (int u = 0; u < 2; ++u) {
        int t = tid + 256*u, j = t >> 6, dd = t & 63;
        float acc = bq[dd];
        const float2* sj2 = (const float2*)(sn + j*64);
        #pragma unroll 8
        for (int d2 = 0; d2 < 32; ++d2) {
            float2 w = g_Wqp[d2*64 + dd];
            float2 s2 = sj2[d2];
            acc += s2.x*w.x + s2.y*w.y;
        }
        g_q[b*512 + t] = acc * SCALE;
    }
}

// ---------------- attention: R5-proven fp16 k/v, in-thread softmax ----------------
__global__ __launch_bounds__(256)
void k_attn() {
    __shared__ float dots[8*DSTR];
    __shared__ float att[8*DSTR];
    __shared__ float redP[8*512];
    __shared__ float redS[64];
    __shared__ int   cnts[4];

    int b = blockIdx.y, chunk = blockIdx.x;
    int tid = threadIdx.x;
    int warp = tid >> 5, lane = tid & 31;
    int jj = lane & 7;
    int gg = lane >> 3;

    if (tid < 4) cnts[tid] = g_cnt[b*(N/TILE_R) + chunk*4 + tid];

    float q[16];
    {
        const float4* qp = (const float4*)(g_q + b*512 + jj*64) + (gg << 2);
        #pragma unroll
        for (int i = 0; i < 4; ++i) {
            float4 t4 = qp[i];
            q[4*i] = t4.x; q[4*i+1] = t4.y; q[4*i+2] = t4.z; q[4*i+3] = t4.w;
        }
    }
    __syncthreads();

    // Phase A: dots (fp16 k)
    #pragma unroll
    for (int s = 0; s < 4; ++s) {
        int nit = (cnts[s] + 7) >> 3;
        const __half* kb = g_kh + ((size_t)(b*(N/TILE_R) + chunk*4 + s) * TILE_R) * 64;
        #pragma unroll 2
        for (int it = 0; it < nit; ++it) {
            int r = it*8 + warp;
            const uint4* kp = (const uint4*)(kb + r*64) + gg*2;
            uint4 u0 = kp[0], u1 = kp[1];
            float d = doth16(u0, u1, q);
            d += __shfl_xor_sync(~0u, d, 8);
            d += __shfl_xor_sync(~0u, d, 16);
            if (gg == 0) dots[jj*DSTR + s*64 + r] = d;
        }
    }
    __syncthreads();

    // Phase B: in-thread softmax; zero att on pad rows
    {
        int s = tid >> 6, r = tid & 63;
        int act = cnts[s];
        int pad8 = (act + 7) & ~7;
        if (r < act) {
            float d[8];
            #pragma unroll
            for (int j = 0; j < 8; ++j) d[j] = dots[j*DSTR + tid];
            float m = d[0];
            #pragma unroll
            for (int j = 1; j < 8; ++j) m = fmaxf(m, d[j]);
            float e[8], sum = 0.f;
            #pragma unroll
            for (int j = 0; j < 8; ++j) { e[j] = __expf(d[j] - m); sum += e[j]; }
            float inv = __fdividef(1.f, sum);
            #pragma unroll
            for (int j = 0; j < 8; ++j) att[j*DSTR + tid] = e[j]*inv + EPSA;
        } else if (r < pad8) {
            #pragma unroll
            for (int j = 0; j < 8; ++j) att[j*DSTR + tid] = 0.f;
        }
    }
    __syncthreads();

    // Phase C: P accumulation (fp16 v)
    float P[16];
    #pragma unroll
    for (int i = 0; i < 16; ++i) P[i] = 0.f;
    float S = 0.f;
    #pragma unroll
    for (int s = 0; s < 4; ++s) {
        int nit = (cnts[s] + 7) >> 3;
        const __half* vb = g_vh + ((size_t)(b*(N/TILE_R) + chunk*4 + s) * TILE_R) * 64;
        #pragma unroll 2
        for (int it = 0; it < nit; ++it) {
            int r = it*8 + warp;
            float a = att[jj*DSTR + s*64 + r];
            S += a;
            const uint4* vp = (const uint4*)(vb + r*64) + gg*2;
            uint4 u0 = vp[0], u1 = vp[1];
            const __half2* h0 = reinterpret_cast<const __half2*>(&u0);
            const __half2* h1 = reinterpret_cast<const __half2*>(&u1);
            #pragma unroll
            for (int i = 0; i < 4; ++i) {
                float2 f = __half22float2(h0[i]);
                P[2*i]   += a*f.x;
                P[2*i+1] += a*f.y;
            }
            #pragma unroll
            for (int i = 0; i < 4; ++i) {
                float2 f = __half22float2(h1[i]);
                P[8+2*i]   += a*f.x;
                P[8+2*i+1] += a*f.y;
            }
        }
    }

    float* rp = redP + warp*512 + jj*64 + (gg << 4);
    #pragma unroll
    for (int i = 0; i < 4; ++i)
        *(float4*)(rp + 4*i) = make_float4(P[4*i], P[4*i+1], P[4*i+2], P[4*i+3]);
    if (gg == 0) redS[warp*8 + jj] = S;
    __syncthreads();

    #pragma unroll
    for (int u = 0; u < 2; ++u) {
        int t = tid + 256*u;
        float s = 0.f;
        #pragma unroll
        for (int w = 0; w < 8; ++w) s += redP[w*512 + t];
        g_Pp[((size_t)b*NB + chunk)*512 + t] = s;
    }
    if (tid < 8) {
        float s = 0.f;
        #pragma unroll
        for (int w = 0; w < 8; ++w) s += redS[w*8 + tid];
        g_Sp[(b*NB + chunk)*8 + tid] = s;
    }
}

// ---------------- slot update: GRU + residual MLP (+ next q); 4 slots/block ----------------
__global__ __launch_bounds__(256)
void k_update(const float* __restrict__ b_ih, const float* __restrict__ b_hh,
              const float* __restrict__ b1, const float* __restrict__ b2,
              const float* __restrict__ ln_ff_w, const float* __restrict__ ln_ff_b,
              const float* __restrict__ ln_s_w, const float* __restrict__ ln_s_b,
              const float* __restrict__ bq,
              float* __restrict__ d_out, int last) {
    __shared__ float upd[256], prev[256], snew[256], ffs[256], hid[512], sfin[256], Ssm[4];
    int b = blockIdx.y, half = blockIdx.x, tid = threadIdx.x;
    int j0 = half * 4;
    int j = tid >> 6, dd = tid & 63;
    int J = j0 + j;

    if (tid < 4) {
        float s = 0.f;
        const float* sp = g_Sp + b*NB*8 + j0 + tid;
        #pragma unroll
        for (int p = 0; p < NB; ++p) s += sp[p*8];
        Ssm[tid] = s;
    }
    float pr;
    {
        float s = 0.f;
        const float* pp = g_Pp + (size_t)b*NB*512 + J*64 + dd;
        #pragma unroll
        for (int p = 0; p < NB; ++p) s += pp[p*512];
        pr = s;
        prev[tid] = g_slots[b*512 + J*64 + dd];
    }
    __syncthreads();
    upd[tid] = pr / Ssm[j];
    __syncthreads();

    // GRU with packed weights
    {
        const float* uj = upd + j*64;
        const float* hj = prev + j*64;
        float xr = b_ih[dd], xz = b_ih[64+dd], xn = b_ih[128+dd];
        float hr = b_hh[dd], hz = b_hh[64+dd], hn = b_hh[128+dd];
        #pragma unroll 8
        for (int d = 0; d < 64; ++d) {
            float uu = uj[d], hh = hj[d];
            float4 wa = __ldg(g_WgA + d*64 + dd);
            float2 wb = __ldg(g_WgB + d*64 + dd);
            xr += uu*wa.x; xz += uu*wa.y; xn += uu*wa.z;
            hr += hh*wa.w; hz += hh*wb.x; hn += hh*wb.y;
        }
        float rg = 1.f/(1.f + __expf(-(xr + hr)));
        float zg = 1.f/(1.f + __expf(-(xz + hz)));
        float t2 = __expf(2.f*(xn + rg*hn));
        float nn = 1.f - 2.f/(t2 + 1.f);
        snew[tid] = (1.f - zg)*nn + zg*prev[tid];
    }
    __syncthreads();
    lnrows(snew, ffs, ln_ff_w, ln_ff_b, tid, 4);
    __syncthreads();
    // MLP layer 1
    {
        int h2 = dd;
        float a0 = b1[2*h2], a1 = b1[2*h2+1];
        const float* fj = ffs + j*64;
        #pragma unroll 8
        for (int d = 0; d < 64; ++d) {
            float2 w = __ldg(g_W1p + d*64 + h2);
            float f = fj[d];
            a0 += f*w.x; a1 += f*w.y;
        }
        hid[j*128 + 2*h2]   = fmaxf(a0, 0.f);
        hid[j*128 + 2*h2+1] = fmaxf(a1, 0.f);
    }
    __syncthreads();
    {
        float acc = b2[dd];
        const float2* hj2 = (const float2*)(hid + j*128);
        #pragma unroll 8
        for (int h2 = 0; h2 < 64; ++h2) {
            float2 w = __ldg(g_W2p + h2*64 + dd);
            float2 hv = hj2[h2];
            acc += hv.x*w.x + hv.y*w.y;
        }
        float o = snew[tid] + acc;
        sfin[tid] = o;
        g_slots[b*512 + J*64 + dd] = o;
        if (last) d_out[b*512 + J*64 + dd] = o;
    }
    if (!last) {
        __syncthreads();
        lnrows(sfin, ffs, ln_s_w, ln_s_b, tid, 4);
        __syncthreads();
        {
            float acc = bq[dd];
            const float2* sj2 = (const float2*)(ffs + j*64);
            #pragma unroll 8
            for (int d2 = 0; d2 < 32; ++d2) {
                float2 w = __ldg(g_Wqp + d2*64 + dd);
                float2 s2 = sj2[d2];
                acc += s2.x*w.x + s2.y*w.y;
            }
            g_q[b*512 + J*64 + dd] = acc * SCALE;
        }
    }
}

// ---------------- launch ----------------
extern "C" void kernel_launch(void* const* d_in, const int* in_sizes, int n_in,
                              void* d_out, int out_size) {
    const float* inputs     = (const float*)d_in[0];
    const int*   mask       = (const int*)  d_in[1];
    const float* noise      = (const float*)d_in[2];
    const float* slots_mu   = (const float*)d_in[3];
    const float* slots_sig  = (const float*)d_in[4];
    const float* Wq         = (const float*)d_in[5];
    const float* bq         = (const float*)d_in[6];
    const float* Wk         = (const float*)d_in[7];
    const float* bk         = (const float*)d_in[8];
    const float* Wv         = (const float*)d_in[9];
    const float* bv         = (const float*)d_in[10];
    const float* W_ih       = (const float*)d_in[11];
    const float* b_ih       = (const float*)d_in[12];
    const float* W_hh       = (const float*)d_in[13];
    const float* b_hh       = (const float*)d_in[14];
    const float* W1         = (const float*)d_in[15];
    const float* b1         = (const float*)d_in[16];
    const float* W2         = (const float*)d_in[17];
    const float* b2         = (const float*)d_in[18];
    const float* ln_in_w    = (const float*)d_in[19];
    const float* ln_in_b    = (const float*)d_in[20];
    const float* ln_s_w     = (const float*)d_in[21];
    const float* ln_s_b     = (const float*)d_in[22];
    const float* ln_ff_w    = (const float*)d_in[23];
    const float* ln_ff_b    = (const float*)d_in[24];
    float* out = (float*)d_out;

    k_prep<<<48, 256>>>(Wk, Wv, W_ih, W_hh, W1, W2, Wq);
    k_ln_kv<<<(B*N)/TILE_R, 256>>>(inputs, mask, bk, bv, ln_in_w, ln_in_b);
    k_init<<<B, 256>>>(noise, slots_mu, slots_sig, ln_s_w, ln_s_b, bq);
    for (int it = 0; it < ITERS; ++it) {
        k_attn<<<dim3(NB, B), 256>>>();
        k_update<<<dim3(2, B), 256>>>(b_ih, b_hh, b1, b2, ln_ff_w, ln_ff_b,
                                      ln_s_w, ln_s_b, bq, out, it == ITERS-1 ? 1 : 0);
    }
}

// round 12
// speedup vs baseline: 1.4825x; 1.0451x over previous
#include <cuda_runtime.h>
#include <cuda_fp16.h>
#include <cstdint>

// ---------------- problem constants ----------------
#define B       64
#define N       4096
#define D       64
#define H       128
#define NS      8
#define ITERS   3
#define EPSA    1e-8f
#define LN_EPS  1e-5f
#define SCALE   0.125f

#define TILE_R  64              // rows per region in kv kernel
#define NB      16              // chunks per batch in attention (256 rows each)
#define DSTR    257             // padded stride for dots/att smem
#define QSTR    66              // padded stride for fp16 q smem

typedef unsigned long long ull;

// ---------------- device scratch ----------------
__device__ __half g_kh[B*N*D];         // compacted per 64-row region, fp16
__device__ __half g_vh[B*N*D];
__device__ int    g_cnt[B*N/TILE_R];   // active rows per region
__device__ float  g_slots[B*NS*D];
__device__ float  g_q[B*NS*D];
__device__ float  g_Pp[B*NB*NS*D];
__device__ float  g_Sp[B*NB*NS];
__device__ ulonglong2 g_wk2v[16*64];   // [d4][c] packed f32x2 pairs
__device__ ulonglong2 g_wv2v[16*64];
__device__ float4 g_WgA[64*64];        // [d][dd] = (Wih_r, Wih_z, Wih_n, Whh_r)
__device__ float2 g_WgB[64*64];        // [d][dd] = (Whh_z, Whh_n)
__device__ float2 g_W1p[64*64];        // [d][h2]
__device__ float2 g_W2p[64*64];        // [h2][dd]
__device__ float2 g_Wqp[32*64];        // [d2][dd]

// ---------------- f32x2 helpers ----------------
__device__ __forceinline__ ull packf2(float x, float y) {
    ull r;
    asm("mov.b64 %0, {%1,%2};" : "=l"(r) : "f"(x), "f"(y));
    return r;
}
__device__ __forceinline__ float2 unpackf2(ull v) {
    float2 f;
    asm("mov.b64 {%0,%1}, %2;" : "=f"(f.x), "=f"(f.y) : "l"(v));
    return f;
}
__device__ __forceinline__ ull ffma2(ull a, ull b, ull c) {
    ull d;
    asm("fma.rn.f32x2 %0, %1, %2, %3;" : "=l"(d) : "l"(a), "l"(b), "l"(c));
    return d;
}
__device__ __forceinline__ uint32_t smem_u32(const void* p) {
    uint32_t a;
    asm("{ .reg .u64 t; cvta.to.shared.u64 t, %1; cvt.u32.u64 %0, t; }" : "=r"(a) : "l"(p));
    return a;
}

// ---------------- merged prep + init ----------------
__global__ __launch_bounds__(256)
void k_prep_init(const float* __restrict__ Wk, const float* __restrict__ Wv,
                 const float* __restrict__ W_ih, const float* __restrict__ W_hh,
                 const float* __restrict__ W1, const float* __restrict__ W2,
                 const float* __restrict__ Wq,
                 const float* __restrict__ noise, const float* __restrict__ mu,
                 const float* __restrict__ sg,
                 const float* __restrict__ ln_s_w, const float* __restrict__ ln_s_b,
                 const float* __restrict__ bq) {
    int tid = threadIdx.x;
    int i = blockIdx.x * 256 + tid;
    // --- prep (weight transposes/packs) ---
    if (i < 1024) {
        int d4 = i >> 6, c = i & 63;
        float4 fk = *(const float4*)(Wk + c*64 + d4*4);
        float4 fv = *(const float4*)(Wv + c*64 + d4*4);
        ulonglong2 k2, v2;
        k2.x = packf2(fk.x, fk.y); k2.y = packf2(fk.z, fk.w);
        v2.x = packf2(fv.x, fv.y); v2.y = packf2(fv.z, fv.w);
        g_wk2v[i] = k2;
        g_wv2v[i] = v2;
    }
    if (i < 4096) {
        int d = i >> 6, x = i & 63;
        g_WgA[i] = make_float4(W_ih[x*64 + d], W_ih[(64+x)*64 + d],
                               W_ih[(128+x)*64 + d], W_hh[x*64 + d]);
        g_WgB[i] = make_float2(W_hh[(64+x)*64 + d], W_hh[(128+x)*64 + d]);
        g_W1p[i] = make_float2(W1[(2*x)*64 + d], W1[(2*x+1)*64 + d]);
        g_W2p[i] = make_float2(W2[x*128 + 2*d], W2[x*128 + 2*d + 1]);
    }
    if (i < 2048) {
        int d2 = i >> 6, dd = i & 63;
        g_Wqp[i] = make_float2(Wq[dd*64 + 2*d2], Wq[dd*64 + 2*d2 + 1]);
    }
    // --- init: slots + LN + q0 (direct Wq reads, no prep dependency) ---
    __shared__ float sl[512], sn[512];
    int b = blockIdx.x;
    #pragma unroll
    for (int u = 0; u < 2; ++u) {
        int t = tid + 256*u, dd = t & 63;
        float s = mu[dd] + sg[dd]*noise[b*512 + t];
        sl[t] = s;
        g_slots[b*512 + t] = s;
    }
    __syncthreads();
    {
        int wp = tid >> 5, lane = tid & 31;
        const float* p = sl + wp*64;
        float v0 = p[lane], v1 = p[lane+32];
        float s = v0 + v1;
        #pragma unroll
        for (int o = 16; o; o >>= 1) s += __shfl_xor_sync(~0u, s, o);
        float mmu = s * (1.f/64.f);
        float d0 = v0 - mmu, d1 = v1 - mmu;
        float q = d0*d0 + d1*d1;
        #pragma unroll
        for (int o = 16; o; o >>= 1) q += __shfl_xor_sync(~0u, q, o);
        float rs = rsqrtf(q * (1.f/64.f) + LN_EPS);
        sn[wp*64 + lane]      = d0*rs*ln_s_w[lane] + ln_s_b[lane];
        sn[wp*64 + lane + 32] = d1*rs*ln_s_w[lane+32] + ln_s_b[lane+32];
    }
    __syncthreads();
    #pragma unroll
    for (int u = 0; u < 2; ++u) {
        int t = tid + 256*u, j = t >> 6, dd = t & 63;
        float acc = bq[dd];
        const float2* sj2 = (const float2*)(sn + j*64);
        #pragma unroll 8
        for (int d2 = 0; d2 < 32; ++d2) {
            float2 w = *(const float2*)(Wq + dd*64 + 2*d2);
            float2 s2 = sj2[d2];
            acc += s2.x*w.x + s2.y*w.y;
        }
        g_q[b*512 + t] = acc * SCALE;
    }
}

// ---------------- K1: mask-compact + shuffle-free LN + k/v GEMM (R11 proven) ----------------
__global__ __launch_bounds__(256, 4)
void k_ln_kv(const float* __restrict__ inputs, const int* __restrict__ mask,
             const float* __restrict__ bk, const float* __restrict__ bv,
             const float* __restrict__ lnw, const float* __restrict__ lnb) {
    __shared__ __align__(16) float xs[TILE_R*64];
    __shared__ float ps[TILE_R*4], pq[TILE_R*4];
    __shared__ float rmu[TILE_R], rrs[TILE_R];
    __shared__ int tpos[TILE_R];
    __shared__ int cmap[TILE_R];
    __shared__ int wc[2];

    int tid = threadIdx.x;
    int lane = tid & 31, warp = tid >> 5;
    size_t row0 = (size_t)blockIdx.x * TILE_R;

    if (tid < 64) {
        int mm = mask[row0 + tid] != 0;
        unsigned bal = __ballot_sync(~0u, mm);
        if (lane == 0) wc[warp] = __popc(bal);
        tpos[tid] = mm ? __popc(bal & ((1u << lane) - 1u)) : -1;
    }
    __syncthreads();
    int act = wc[0] + wc[1];
    if (tid < 64 && tpos[tid] >= 0)
        cmap[tpos[tid] + (tid >= 32 ? wc[0] : 0)] = tid;
    if (tid == 0) g_cnt[blockIdx.x] = act;
    __syncthreads();

    // LN-a: gather active rows coalesced (16 threads per row)
    {
        int rph = tid >> 4;
        int quad = tid & 15;
        for (int base = 0; base < act; base += 16) {
            int ci = base + rph;
            if (ci < act) {
                int r = cmap[ci];
                *(float4*)(xs + ci*64 + quad*4) =
                    *(const float4*)(inputs + (row0 + r)*64 + quad*4);
            }
        }
    }
    __syncthreads();

    // LN-b: per-(row, quarter) partials
    {
        int ci = tid >> 2, q = tid & 3;
        if (ci < act) {
            const float4* p = (const float4*)(xs + ci*64 + q*16);
            float s = 0.f, ss = 0.f;
            #pragma unroll
            for (int i = 0; i < 4; ++i) {
                float4 v = p[i];
                s  += (v.x + v.y) + (v.z + v.w);
                ss += (v.x*v.x + v.y*v.y) + (v.z*v.z + v.w*v.w);
            }
            ps[ci*4 + q] = s;
            pq[ci*4 + q] = ss;
        }
    }
    __syncthreads();

    if (tid < act) {
        float s  = (ps[tid*4] + ps[tid*4+1]) + (ps[tid*4+2] + ps[tid*4+3]);
        float ss = (pq[tid*4] + pq[tid*4+1]) + (pq[tid*4+2] + pq[tid*4+3]);
        float mu  = s * (1.f/64.f);
        float var = ss * (1.f/64.f) - mu*mu;
        rmu[tid] = mu;
        rrs[tid] = rsqrtf(var + LN_EPS);
    }
    __syncthreads();

    {
        int tot = act * 16;
        for (int e = tid; e < tot; e += 256) {
            int ci = e >> 4, q = e & 15;
            float4 v = *(float4*)(xs + ci*64 + q*4);
            float mu = rmu[ci], rs = rrs[ci];
            float4 w4 = __ldg((const float4*)lnw + q);
            float4 b4 = __ldg((const float4*)lnb + q);
            v.x = (v.x - mu)*rs*w4.x + b4.x;
            v.y = (v.y - mu)*rs*w4.y + b4.y;
            v.z = (v.z - mu)*rs*w4.z + b4.z;
            v.w = (v.w - mu)*rs*w4.w + b4.w;
            *(float4*)(xs + ci*64 + q*4) = v;
        }
    }
    __syncthreads();

    int c  = tid & 63;
    int rb = tid >> 6;
    float bkc = bk[c], bvc = bv[c];
    const ulonglong2* xs2 = reinterpret_cast<const ulonglong2*>(xs);
    int G = (act + 31) >> 5;
    for (int g = 0; g < G; ++g) {
        ull ak[8], av[8];
        #pragma unroll
        for (int t = 0; t < 8; ++t) { ak[t] = 0ull; av[t] = 0ull; }
        #pragma unroll
        for (int d4 = 0; d4 < 16; ++d4) {
            ulonglong2 wk = __ldg(g_wk2v + d4*64 + c);
            ulonglong2 wv = __ldg(g_wv2v + d4*64 + c);
            #pragma unroll
            for (int t = 0; t < 8; ++t) {
                int ci = g*32 + rb + 4*t;
                ulonglong2 x = xs2[ci*16 + d4];
                ak[t] = ffma2(x.x, wk.x, ak[t]);
                ak[t] = ffma2(x.y, wk.y, ak[t]);
                av[t] = ffma2(x.x, wv.x, av[t]);
                av[t] = ffma2(x.y, wv.y, av[t]);
            }
        }
        #pragma unroll
        for (int t = 0; t < 8; ++t) {
            int ci = g*32 + rb + 4*t;
            if (ci < act) {
                float2 k2 = unpackf2(ak[t]);
                float2 v2 = unpackf2(av[t]);
                g_kh[(row0 + ci)*64 + c] = __float2half_rn(k2.x + k2.y + bkc);
                g_vh[(row0 + ci)*64 + c] = __float2half_rn(v2.x + v2.y + bvc);
            }
        }
    }
    // rows [act, 64) never written -> stay zero (bss): dots=0, padded loops safe
}

// ---------------- LN over slot rows ----------------
__device__ __forceinline__ void lnrows(const float* in, float* out,
                                       const float* __restrict__ w,
                                       const float* __restrict__ bia, int tid, int nrows) {
    int wp = tid >> 5, lane = tid & 31;
    if (wp >= nrows) return;
    const float* p = in + wp*64;
    float v0 = p[lane], v1 = p[lane+32];
    float s = v0 + v1;
    #pragma unroll
    for (int o = 16; o; o >>= 1) s += __shfl_xor_sync(~0u, s, o);
    float mu = s * (1.f/64.f);
    float d0 = v0 - mu, d1 = v1 - mu;
    float q = d0*d0 + d1*d1;
    #pragma unroll
    for (int o = 16; o; o >>= 1) q += __shfl_xor_sync(~0u, q, o);
    float rs = rsqrtf(q * (1.f/64.f) + LN_EPS);
    out[wp*64 + lane]      = d0*rs*w[lane] + bia[lane];
    out[wp*64 + lane + 32] = d1*rs*w[lane+32] + bia[lane+32];
}

// ---------------- attention: HMMA phase A + scalar phase C ----------------
__global__ __launch_bounds__(256)
void k_attn() {
    // overlay: staging (32KB) THEN {att (8*DSTR floats) | redP (4096) | redS (64)}
    __shared__ __align__(16) char sbuf[32*1024];
    __shared__ __align__(16) float dots[8*DSTR];
    __shared__ __align__(4)  __half qh[8*QSTR];
    __shared__ int cnts[4];

    __half* stg  = (__half*)sbuf;                 // 256 rows x 64 halves (swizzled)
    float*  att  = (float*)sbuf;
    float*  redP = (float*)(sbuf + 8*DSTR*sizeof(float));
    float*  redS = redP + 4096;

    int b = blockIdx.y, chunk = blockIdx.x;
    int tid = threadIdx.x;
    int warp = tid >> 5, lane = tid & 31;
    int jj = lane & 7;
    int gg = lane >> 3;

    if (tid < 4) cnts[tid] = g_cnt[b*(N/TILE_R) + chunk*4 + tid];

    // stage k tile: 256 rows x 8 uint4, XOR swizzle on 16B groups
    {
        const uint4* src = (const uint4*)(g_kh + ((size_t)b*N + chunk*256)*64);
        #pragma unroll
        for (int e0 = 0; e0 < 2048; e0 += 256) {
            int e = e0 + tid;
            int ci = e >> 3, q = e & 7;
            uint4 v = __ldg(src + e);
            *(uint4*)(sbuf + ci*128 + ((q ^ (ci & 7)) << 4)) = v;
        }
    }
    // q -> fp16 smem (padded stride)
    for (int e = tid; e < 512; e += 256) {
        int j = e >> 6, d = e & 63;
        qh[j*QSTR + d] = __float2half_rn(g_q[b*512 + e]);
    }
    __syncthreads();

    // Phase A: mma. warp w covers rows w*32 .. w*32+31 (region s = w>>1)
    {
        uint32_t stg_base = smem_u32(stg);
        int R0 = warp * 32;
        float d0[4] = {0.f,0.f,0.f,0.f};
        float d1[4] = {0.f,0.f,0.f,0.f};
        int j = lane >> 2, kb = (lane & 3) * 2;
        #pragma unroll
        for (int ks = 0; ks < 4; ++ks) {
            uint32_t b0 = *(const uint32_t*)(qh + j*QSTR + 16*ks + kb);
            uint32_t b1 = *(const uint32_t*)(qh + j*QSTR + 16*ks + kb + 8);
            #pragma unroll
            for (int tile = 0; tile < 2; ++tile) {
                int lr = R0 + tile*16 + (lane & 15);
                int qq = 2*ks + (lane >> 4);
                uint32_t addr = stg_base + lr*128 + ((qq ^ (lr & 7)) << 4);
                uint32_t a0, a1, a2, a3;
                asm volatile("ldmatrix.sync.aligned.m8n8.x4.shared.b16 {%0,%1,%2,%3}, [%4];"
                             : "=r"(a0), "=r"(a1), "=r"(a2), "=r"(a3) : "r"(addr));
                float* dd = tile ? d1 : d0;
                asm volatile("mma.sync.aligned.m16n8k16.row.col.f32.f16.f16.f32 "
                             "{%0,%1,%2,%3}, {%4,%5,%6,%7}, {%8,%9}, {%0,%1,%2,%3};"
                             : "+f"(dd[0]), "+f"(dd[1]), "+f"(dd[2]), "+f"(dd[3])
                             : "r"(a0), "r"(a1), "r"(a2), "r"(a3), "r"(b0), "r"(b1));
            }
        }
        // D fragment -> dots: thread holds rows (lane>>2), (lane>>2)+8; cols 2*(lane&3), +1
        int s = warp >> 1;
        int rbase = (warp & 1) * 32;
        int trow = lane >> 2;
        int col = (lane & 3) * 2;
        #pragma unroll
        for (int tile = 0; tile < 2; ++tile) {
            float* dd = tile ? d1 : d0;
            int r = rbase + tile*16 + trow;
            dots[(col  )*DSTR + s*64 + r    ] = dd[0];
            dots[(col+1)*DSTR + s*64 + r    ] = dd[1];
            dots[(col  )*DSTR + s*64 + r + 8] = dd[2];
            dots[(col+1)*DSTR + s*64 + r + 8] = dd[3];
        }
    }
    __syncthreads();

    // Phase B: in-thread softmax (writes att overlay; staging dead)
    {
        int s = tid >> 6, r = tid & 63;
        int act = cnts[s];
        int pad8 = (act + 7) & ~7;
        if (r < act) {
            float d[8];
            #pragma unroll
            for (int j2 = 0; j2 < 8; ++j2) d[j2] = dots[j2*DSTR + tid];
            float m = d[0];
            #pragma unroll
            for (int j2 = 1; j2 < 8; ++j2) m = fmaxf(m, d[j2]);
            float e[8], sum = 0.f;
            #pragma unroll
            for (int j2 = 0; j2 < 8; ++j2) { e[j2] = __expf(d[j2] - m); sum += e[j2]; }
            float inv = __fdividef(1.f, sum);
            #pragma unroll
            for (int j2 = 0; j2 < 8; ++j2) att[j2*DSTR + tid] = e[j2]*inv + EPSA;
        } else if (r < pad8) {
            #pragma unroll
            for (int j2 = 0; j2 < 8; ++j2) att[j2*DSTR + tid] = 0.f;
        }
    }
    __syncthreads();

    // Phase C: P accumulation (fp16 v, scalar — R11 proven)
    float P[16];
    #pragma unroll
    for (int i = 0; i < 16; ++i) P[i] = 0.f;
    float S = 0.f;
    #pragma unroll
    for (int s = 0; s < 4; ++s) {
        int nit = (cnts[s] + 7) >> 3;
        const __half* vb = g_vh + ((size_t)(b*(N/TILE_R) + chunk*4 + s) * TILE_R) * 64;
        #pragma unroll 2
        for (int it = 0; it < nit; ++it) {
            int r = it*8 + warp;
            float a = att[jj*DSTR + s*64 + r];
            S += a;
            const uint4* vp = (const uint4*)(vb + r*64) + gg*2;
            uint4 u0 = vp[0], u1 = vp[1];
            const __half2* h0 = reinterpret_cast<const __half2*>(&u0);
            const __half2* h1 = reinterpret_cast<const __half2*>(&u1);
            #pragma unroll
            for (int i = 0; i < 4; ++i) {
                float2 f = __half22float2(h0[i]);
                P[2*i]   += a*f.x;
                P[2*i+1] += a*f.y;
            }
            #pragma unroll
            for (int i = 0; i < 4; ++i) {
                float2 f = __half22float2(h1[i]);
                P[8+2*i]   += a*f.x;
                P[8+2*i+1] += a*f.y;
            }
        }
    }

    float* rp = redP + warp*512 + jj*64 + (gg << 4);
    #pragma unroll
    for (int i = 0; i < 4; ++i)
        *(float4*)(rp + 4*i) = make_float4(P[4*i], P[4*i+1], P[4*i+2], P[4*i+3]);
    if (gg == 0) redS[warp*8 + jj] = S;
    __syncthreads();

    #pragma unroll
    for (int u = 0; u < 2; ++u) {
        int t = tid + 256*u;
        float s = 0.f;
        #pragma unroll
        for (int w = 0; w < 8; ++w) s += redP[w*512 + t];
        g_Pp[((size_t)b*NB + chunk)*512 + t] = s;
    }
    if (tid < 8) {
        float s = 0.f;
        #pragma unroll
        for (int w = 0; w < 8; ++w) s += redS[w*8 + tid];
        g_Sp[(b*NB + chunk)*8 + tid] = s;
    }
}

// ---------------- slot update: GRU + residual MLP (+ next q); 4 slots/block ----------------
__global__ __launch_bounds__(256)
void k_update(const float* __restrict__ b_ih, const float* __restrict__ b_hh,
              const float* __restrict__ b1, const float* __restrict__ b2,
              const float* __restrict__ ln_ff_w, const float* __restrict__ ln_ff_b,
              const float* __restrict__ ln_s_w, const float* __restrict__ ln_s_b,
              const float* __restrict__ bq,
              float* __restrict__ d_out, int last) {
    __shared__ float upd[256], prev[256], snew[256], ffs[256], hid[512], sfin[256], Ssm[4];
    int b = blockIdx.y, half = blockIdx.x, tid = threadIdx.x;
    int j0 = half * 4;
    int j = tid >> 6, dd = tid & 63;
    int J = j0 + j;

    if (tid < 4) {
        float s = 0.f;
        const float* sp = g_Sp + b*NB*8 + j0 + tid;
        #pragma unroll
        for (int p = 0; p < NB; ++p) s += sp[p*8];
        Ssm[tid] = s;
    }
    float pr;
    {
        float s = 0.f;
        const float* pp = g_Pp + (size_t)b*NB*512 + J*64 + dd;
        #pragma unroll
        for (int p = 0; p < NB; ++p) s += pp[p*512];
        pr = s;
        prev[tid] = g_slots[b*512 + J*64 + dd];
    }
    __syncthreads();
    upd[tid] = pr / Ssm[j];
    __syncthreads();

    {
        const float* uj = upd + j*64;
        const float* hj = prev + j*64;
        float xr = b_ih[dd], xz = b_ih[64+dd], xn = b_ih[128+dd];
        float hr = b_hh[dd], hz = b_hh[64+dd], hn = b_hh[128+dd];
        #pragma unroll 8
        for (int d = 0; d < 64; ++d) {
            float uu = uj[d], hh = hj[d];
            float4 wa = __ldg(g_WgA + d*64 + dd);
            float2 wb = __ldg(g_WgB + d*64 + dd);
            xr += uu*wa.x; xz += uu*wa.y; xn += uu*wa.z;
            hr += hh*wa.w; hz += hh*wb.x; hn += hh*wb.y;
        }
        float rg = 1.f/(1.f + __expf(-(xr + hr)));
        float zg = 1.f/(1.f + __expf(-(xz + hz)));
        float t2 = __expf(2.f*(xn + rg*hn));
        float nn = 1.f - 2.f/(t2 + 1.f);
        snew[tid] = (1.f - zg)*nn + zg*prev[tid];
    }
    __syncthreads();
    lnrows(snew, ffs, ln_ff_w, ln_ff_b, tid, 4);
    __syncthreads();
    {
        int h2 = dd;
        float a0 = b1[2*h2], a1 = b1[2*h2+1];
        const float* fj = ffs + j*64;
        #pragma unroll 8
        for (int d = 0; d < 64; ++d) {
            float2 w = __ldg(g_W1p + d*64 + h2);
            float f = fj[d];
            a0 += f*w.x; a1 += f*w.y;
        }
        hid[j*128 + 2*h2]   = fmaxf(a0, 0.f);
        hid[j*128 + 2*h2+1] = fmaxf(a1, 0.f);
    }
    __syncthreads();
    {
        float acc = b2[dd];
        const float2* hj2 = (const float2*)(hid + j*128);
        #pragma unroll 8
        for (int h2 = 0; h2 < 64; ++h2) {
            float2 w = __ldg(g_W2p + h2*64 + dd);
            float2 hv = hj2[h2];
            acc += hv.x*w.x + hv.y*w.y;
        }
        float o = snew[tid] + acc;
        sfin[tid] = o;
        g_slots[b*512 + J*64 + dd] = o;
        if (last) d_out[b*512 + J*64 + dd] = o;
    }
    if (!last) {
        __syncthreads();
        lnrows(sfin, ffs, ln_s_w, ln_s_b, tid, 4);
        __syncthreads();
        {
            float acc = bq[dd];
            const float2* sj2 = (const float2*)(ffs + j*64);
            #pragma unroll 8
            for (int d2 = 0; d2 < 32; ++d2) {
                float2 w = __ldg(g_Wqp + d2*64 + dd);
                float2 s2 = sj2[d2];
                acc += s2.x*w.x + s2.y*w.y;
            }
            g_q[b*512 + J*64 + dd] = acc * SCALE;
        }
    }
}

// ---------------- launch ----------------
extern "C" void kernel_launch(void* const* d_in, const int* in_sizes, int n_in,
                              void* d_out, int out_size) {
    const float* inputs     = (const float*)d_in[0];
    const int*   mask       = (const int*)  d_in[1];
    const float* noise      = (const float*)d_in[2];
    const float* slots_mu   = (const float*)d_in[3];
    const float* slots_sig  = (const float*)d_in[4];
    const float* Wq         = (const float*)d_in[5];
    const float* bq         = (const float*)d_in[6];
    const float* Wk         = (const float*)d_in[7];
    const float* bk         = (const float*)d_in[8];
    const float* Wv         = (const float*)d_in[9];
    const float* bv         = (const float*)d_in[10];
    const float* W_ih       = (const float*)d_in[11];
    const float* b_ih       = (const float*)d_in[12];
    const float* W_hh       = (const float*)d_in[13];
    const float* b_hh       = (const float*)d_in[14];
    const float* W1         = (const float*)d_in[15];
    const float* b1         = (const float*)d_in[16];
    const float* W2         = (const float*)d_in[17];
    const float* b2         = (const float*)d_in[18];
    const float* ln_in_w    = (const float*)d_in[19];
    const float* ln_in_b    = (const float*)d_in[20];
    const float* ln_s_w     = (const float*)d_in[21];
    const float* ln_s_b     = (const float*)d_in[22];
    const float* ln_ff_w    = (const float*)d_in[23];
    const float* ln_ff_b    = (const float*)d_in[24];
    float* out = (float*)d_out;

    k_prep_init<<<64, 256>>>(Wk, Wv, W_ih, W_hh, W1, W2, Wq,
                             noise, slots_mu, slots_sig, ln_s_w, ln_s_b, bq);
    k_ln_kv<<<(B*N)/TILE_R, 256>>>(inputs, mask, bk, bv, ln_in_w, ln_in_b);
    for (int it = 0; it < ITERS; ++it) {
        k_attn<<<dim3(NB, B), 256>>>();
        k_update<<<dim3(2, B), 256>>>(b_ih, b_hh, b1, b2, ln_ff_w, ln_ff_b,
                                      ln_s_w, ln_s_b, bq, out, it == ITERS-1 ? 1 : 0);
    }
}

// round 13
// speedup vs baseline: 1.8525x; 1.2496x over previous
#include <cuda_runtime.h>
#include <cuda_fp16.h>
#include <cstdint>

// ---------------- problem constants ----------------
#define B       64
#define N       4096
#define D       64
#define H       128
#define NS      8
#define ITERS   3
#define EPSA    1e-8f
#define LN_EPS  1e-5f
#define SCALE   0.125f

#define TILE_R  64
#define NB      16
#define DSTR    257
#define QSTR    66

typedef unsigned long long ull;

// ---------------- device scratch ----------------
__device__ __half g_kh[B*N*D];
__device__ __half g_vh[B*N*D];
__device__ int    g_cnt[B*N/TILE_R];
__device__ float  g_slots[B*NS*D];
__device__ float  g_q[B*NS*D];
__device__ float  g_Pp[B*NB*NS*D];
__device__ float  g_Sp[B*NB*NS];
__device__ ulonglong2 g_wk2v[16*64];
__device__ ulonglong2 g_wv2v[16*64];
__device__ float4 g_WgA[64*64];        // [d][dd] = (Wih_r, Wih_z, Wih_n, Whh_r)
__device__ float2 g_WgB[64*64];        // [d][dd] = (Whh_z, Whh_n)
__device__ float2 g_W1p[64*64];        // [d][h2]
__device__ float2 g_W2p[64*64];        // [h2][dd]
__device__ float2 g_Wqp[32*64];        // [d2][dd]

// ---------------- helpers ----------------
__device__ __forceinline__ ull packf2(float x, float y) {
    ull r;
    asm("mov.b64 %0, {%1,%2};" : "=l"(r) : "f"(x), "f"(y));
    return r;
}
__device__ __forceinline__ float2 unpackf2(ull v) {
    float2 f;
    asm("mov.b64 {%0,%1}, %2;" : "=f"(f.x), "=f"(f.y) : "l"(v));
    return f;
}
__device__ __forceinline__ ull ffma2(ull a, ull b, ull c) {
    ull d;
    asm("fma.rn.f32x2 %0, %1, %2, %3;" : "=l"(d) : "l"(a), "l"(b), "l"(c));
    return d;
}
__device__ __forceinline__ uint32_t smem_u32(const void* p) {
    uint32_t a;
    asm("{ .reg .u64 t; cvta.to.shared.u64 t, %1; cvt.u32.u64 %0, t; }" : "=r"(a) : "l"(p));
    return a;
}

// ---------------- merged prep + init ----------------
__global__ __launch_bounds__(256)
void k_prep_init(const float* __restrict__ Wk, const float* __restrict__ Wv,
                 const float* __restrict__ W_ih, const float* __restrict__ W_hh,
                 const float* __restrict__ W1, const float* __restrict__ W2,
                 const float* __restrict__ Wq,
                 const float* __restrict__ noise, const float* __restrict__ mu,
                 const float* __restrict__ sg,
                 const float* __restrict__ ln_s_w, const float* __restrict__ ln_s_b,
                 const float* __restrict__ bq) {
    int tid = threadIdx.x;
    int i = blockIdx.x * 256 + tid;
    if (i < 1024) {
        int d4 = i >> 6, c = i & 63;
        float4 fk = *(const float4*)(Wk + c*64 + d4*4);
        float4 fv = *(const float4*)(Wv + c*64 + d4*4);
        ulonglong2 k2, v2;
        k2.x = packf2(fk.x, fk.y); k2.y = packf2(fk.z, fk.w);
        v2.x = packf2(fv.x, fv.y); v2.y = packf2(fv.z, fv.w);
        g_wk2v[i] = k2;
        g_wv2v[i] = v2;
    }
    if (i < 4096) {
        int d = i >> 6, x = i & 63;
        g_WgA[i] = make_float4(W_ih[x*64 + d], W_ih[(64+x)*64 + d],
                               W_ih[(128+x)*64 + d], W_hh[x*64 + d]);
        g_WgB[i] = make_float2(W_hh[(64+x)*64 + d], W_hh[(128+x)*64 + d]);
        g_W1p[i] = make_float2(W1[(2*x)*64 + d], W1[(2*x+1)*64 + d]);
        g_W2p[i] = make_float2(W2[x*128 + 2*d], W2[x*128 + 2*d + 1]);
    }
    if (i < 2048) {
        int d2 = i >> 6, dd = i & 63;
        g_Wqp[i] = make_float2(Wq[dd*64 + 2*d2], Wq[dd*64 + 2*d2 + 1]);
    }
    // init slots + LN + q0
    __shared__ float sl[512], sn[512];
    int b = blockIdx.x;
    #pragma unroll
    for (int u = 0; u < 2; ++u) {
        int t = tid + 256*u, dd = t & 63;
        float s = mu[dd] + sg[dd]*noise[b*512 + t];
        sl[t] = s;
        g_slots[b*512 + t] = s;
    }
    __syncthreads();
    {
        int wp = tid >> 5, lane = tid & 31;
        const float* p = sl + wp*64;
        float v0 = p[lane], v1 = p[lane+32];
        float s = v0 + v1;
        #pragma unroll
        for (int o = 16; o; o >>= 1) s += __shfl_xor_sync(~0u, s, o);
        float mmu = s * (1.f/64.f);
        float d0 = v0 - mmu, d1 = v1 - mmu;
        float q = d0*d0 + d1*d1;
        #pragma unroll
        for (int o = 16; o; o >>= 1) q += __shfl_xor_sync(~0u, q, o);
        float rs = rsqrtf(q * (1.f/64.f) + LN_EPS);
        sn[wp*64 + lane]      = d0*rs*ln_s_w[lane] + ln_s_b[lane];
        sn[wp*64 + lane + 32] = d1*rs*ln_s_w[lane+32] + ln_s_b[lane+32];
    }
    __syncthreads();
    #pragma unroll
    for (int u = 0; u < 2; ++u) {
        int t = tid + 256*u, j = t >> 6, dd = t & 63;
        float acc = bq[dd];
        const float2* sj2 = (const float2*)(sn + j*64);
        #pragma unroll 8
        for (int d2 = 0; d2 < 32; ++d2) {
            float2 w = *(const float2*)(Wq + dd*64 + 2*d2);
            float2 s2 = sj2[d2];
            acc += s2.x*w.x + s2.y*w.y;
        }
        g_q[b*512 + t] = acc * SCALE;
    }
}

// ---------------- K1: mask-compact + shuffle-free LN + k/v GEMM (R11 proven) ----------------
__global__ __launch_bounds__(256, 4)
void k_ln_kv(const float* __restrict__ inputs, const int* __restrict__ mask,
             const float* __restrict__ bk, const float* __restrict__ bv,
             const float* __restrict__ lnw, const float* __restrict__ lnb) {
    __shared__ __align__(16) float xs[TILE_R*64];
    __shared__ float ps[TILE_R*4], pq[TILE_R*4];
    __shared__ float rmu[TILE_R], rrs[TILE_R];
    __shared__ int tpos[TILE_R];
    __shared__ int cmap[TILE_R];
    __shared__ int wc[2];

    int tid = threadIdx.x;
    int lane = tid & 31, warp = tid >> 5;
    size_t row0 = (size_t)blockIdx.x * TILE_R;

    if (tid < 64) {
        int mm = mask[row0 + tid] != 0;
        unsigned bal = __ballot_sync(~0u, mm);
        if (lane == 0) wc[warp] = __popc(bal);
        tpos[tid] = mm ? __popc(bal & ((1u << lane) - 1u)) : -1;
    }
    __syncthreads();
    int act = wc[0] + wc[1];
    if (tid < 64 && tpos[tid] >= 0)
        cmap[tpos[tid] + (tid >= 32 ? wc[0] : 0)] = tid;
    if (tid == 0) g_cnt[blockIdx.x] = act;
    __syncthreads();

    {
        int rph = tid >> 4;
        int quad = tid & 15;
        for (int base = 0; base < act; base += 16) {
            int ci = base + rph;
            if (ci < act) {
                int r = cmap[ci];
                *(float4*)(xs + ci*64 + quad*4) =
                    *(const float4*)(inputs + (row0 + r)*64 + quad*4);
            }
        }
    }
    __syncthreads();

    {
        int ci = tid >> 2, q = tid & 3;
        if (ci < act) {
            const float4* p = (const float4*)(xs + ci*64 + q*16);
            float s = 0.f, ss = 0.f;
            #pragma unroll
            for (int i = 0; i < 4; ++i) {
                float4 v = p[i];
                s  += (v.x + v.y) + (v.z + v.w);
                ss += (v.x*v.x + v.y*v.y) + (v.z*v.z + v.w*v.w);
            }
            ps[ci*4 + q] = s;
            pq[ci*4 + q] = ss;
        }
    }
    __syncthreads();

    if (tid < act) {
        float s  = (ps[tid*4] + ps[tid*4+1]) + (ps[tid*4+2] + ps[tid*4+3]);
        float ss = (pq[tid*4] + pq[tid*4+1]) + (pq[tid*4+2] + pq[tid*4+3]);
        float mu  = s * (1.f/64.f);
        float var = ss * (1.f/64.f) - mu*mu;
        rmu[tid] = mu;
        rrs[tid] = rsqrtf(var + LN_EPS);
    }
    __syncthreads();

    {
        int tot = act * 16;
        for (int e = tid; e < tot; e += 256) {
            int ci = e >> 4, q = e & 15;
            float4 v = *(float4*)(xs + ci*64 + q*4);
            float mu = rmu[ci], rs = rrs[ci];
            float4 w4 = __ldg((const float4*)lnw + q);
            float4 b4 = __ldg((const float4*)lnb + q);
            v.x = (v.x - mu)*rs*w4.x + b4.x;
            v.y = (v.y - mu)*rs*w4.y + b4.y;
            v.z = (v.z - mu)*rs*w4.z + b4.z;
            v.w = (v.w - mu)*rs*w4.w + b4.w;
            *(float4*)(xs + ci*64 + q*4) = v;
        }
    }
    __syncthreads();

    int c  = tid & 63;
    int rb = tid >> 6;
    float bkc = bk[c], bvc = bv[c];
    const ulonglong2* xs2 = reinterpret_cast<const ulonglong2*>(xs);
    int G = (act + 31) >> 5;
    for (int g = 0; g < G; ++g) {
        ull ak[8], av[8];
        #pragma unroll
        for (int t = 0; t < 8; ++t) { ak[t] = 0ull; av[t] = 0ull; }
        #pragma unroll
        for (int d4 = 0; d4 < 16; ++d4) {
            ulonglong2 wk = __ldg(g_wk2v + d4*64 + c);
            ulonglong2 wv = __ldg(g_wv2v + d4*64 + c);
            #pragma unroll
            for (int t = 0; t < 8; ++t) {
                int ci = g*32 + rb + 4*t;
                ulonglong2 x = xs2[ci*16 + d4];
                ak[t] = ffma2(x.x, wk.x, ak[t]);
                ak[t] = ffma2(x.y, wk.y, ak[t]);
                av[t] = ffma2(x.x, wv.x, av[t]);
                av[t] = ffma2(x.y, wv.y, av[t]);
            }
        }
        #pragma unroll
        for (int t = 0; t < 8; ++t) {
            int ci = g*32 + rb + 4*t;
            if (ci < act) {
                float2 k2 = unpackf2(ak[t]);
                float2 v2 = unpackf2(av[t]);
                g_kh[(row0 + ci)*64 + c] = __float2half_rn(k2.x + k2.y + bkc);
                g_vh[(row0 + ci)*64 + c] = __float2half_rn(v2.x + v2.y + bvc);
            }
        }
    }
}

// ---------------- LN over slot rows ----------------
__device__ __forceinline__ void lnrows(const float* in, float* out,
                                       const float* __restrict__ w,
                                       const float* __restrict__ bia, int tid, int nrows) {
    int wp = tid >> 5, lane = tid & 31;
    if (wp >= nrows) return;
    const float* p = in + wp*64;
    float v0 = p[lane], v1 = p[lane+32];
    float s = v0 + v1;
    #pragma unroll
    for (int o = 16; o; o >>= 1) s += __shfl_xor_sync(~0u, s, o);
    float mu = s * (1.f/64.f);
    float d0 = v0 - mu, d1 = v1 - mu;
    float q = d0*d0 + d1*d1;
    #pragma unroll
    for (int o = 16; o; o >>= 1) q += __shfl_xor_sync(~0u, q, o);
    float rs = rsqrtf(q * (1.f/64.f) + LN_EPS);
    out[wp*64 + lane]      = d0*rs*w[lane] + bia[lane];
    out[wp*64 + lane + 32] = d1*rs*w[lane+32] + bia[lane+32];
}

// ---------------- attention: HMMA phase A + scalar phase C (R12 proven) ----------------
__global__ __launch_bounds__(256)
void k_attn() {
    __shared__ __align__(16) char sbuf[32*1024];
    __shared__ __align__(16) float dots[8*DSTR];
    __shared__ __align__(4)  __half qh[8*QSTR];
    __shared__ int cnts[4];

    __half* stg  = (__half*)sbuf;
    float*  att  = (float*)sbuf;
    float*  redP = (float*)(sbuf + 8*DSTR*sizeof(float));
    float*  redS = redP + 4096;

    int b = blockIdx.y, chunk = blockIdx.x;
    int tid = threadIdx.x;
    int warp = tid >> 5, lane = tid & 31;
    int jj = lane & 7;
    int gg = lane >> 3;

    if (tid < 4) cnts[tid] = g_cnt[b*(N/TILE_R) + chunk*4 + tid];

    {
        const uint4* src = (const uint4*)(g_kh + ((size_t)b*N + chunk*256)*64);
        #pragma unroll
        for (int e0 = 0; e0 < 2048; e0 += 256) {
            int e = e0 + tid;
            int ci = e >> 3, q = e & 7;
            uint4 v = __ldg(src + e);
            *(uint4*)(sbuf + ci*128 + ((q ^ (ci & 7)) << 4)) = v;
        }
    }
    for (int e = tid; e < 512; e += 256) {
        int j = e >> 6, d = e & 63;
        qh[j*QSTR + d] = __float2half_rn(g_q[b*512 + e]);
    }
    __syncthreads();

    {
        uint32_t stg_base = smem_u32(stg);
        int R0 = warp * 32;
        float d0[4] = {0.f,0.f,0.f,0.f};
        float d1[4] = {0.f,0.f,0.f,0.f};
        int j = lane >> 2, kb = (lane & 3) * 2;
        #pragma unroll
        for (int ks = 0; ks < 4; ++ks) {
            uint32_t b0 = *(const uint32_t*)(qh + j*QSTR + 16*ks + kb);
            uint32_t b1 = *(const uint32_t*)(qh + j*QSTR + 16*ks + kb + 8);
            #pragma unroll
            for (int tile = 0; tile < 2; ++tile) {
                int lr = R0 + tile*16 + (lane & 15);
                int qq = 2*ks + (lane >> 4);
                uint32_t addr = stg_base + lr*128 + ((qq ^ (lr & 7)) << 4);
                uint32_t a0, a1, a2, a3;
                asm volatile("ldmatrix.sync.aligned.m8n8.x4.shared.b16 {%0,%1,%2,%3}, [%4];"
                             : "=r"(a0), "=r"(a1), "=r"(a2), "=r"(a3) : "r"(addr));
                float* dd = tile ? d1 : d0;
                asm volatile("mma.sync.aligned.m16n8k16.row.col.f32.f16.f16.f32 "
                             "{%0,%1,%2,%3}, {%4,%5,%6,%7}, {%8,%9}, {%0,%1,%2,%3};"
                             : "+f"(dd[0]), "+f"(dd[1]), "+f"(dd[2]), "+f"(dd[3])
                             : "r"(a0), "r"(a1), "r"(a2), "r"(a3), "r"(b0), "r"(b1));
            }
        }
        int s = warp >> 1;
        int rbase = (warp & 1) * 32;
        int trow = lane >> 2;
        int col = (lane & 3) * 2;
        #pragma unroll
        for (int tile = 0; tile < 2; ++tile) {
            float* dd = tile ? d1 : d0;
            int r = rbase + tile*16 + trow;
            dots[(col  )*DSTR + s*64 + r    ] = dd[0];
            dots[(col+1)*DSTR + s*64 + r    ] = dd[1];
            dots[(col  )*DSTR + s*64 + r + 8] = dd[2];
            dots[(col+1)*DSTR + s*64 + r + 8] = dd[3];
        }
    }
    __syncthreads();

    {
        int s = tid >> 6, r = tid & 63;
        int act = cnts[s];
        int pad8 = (act + 7) & ~7;
        if (r < act) {
            float d[8];
            #pragma unroll
            for (int j2 = 0; j2 < 8; ++j2) d[j2] = dots[j2*DSTR + tid];
            float m = d[0];
            #pragma unroll
            for (int j2 = 1; j2 < 8; ++j2) m = fmaxf(m, d[j2]);
            float e[8], sum = 0.f;
            #pragma unroll
            for (int j2 = 0; j2 < 8; ++j2) { e[j2] = __expf(d[j2] - m); sum += e[j2]; }
            float inv = __fdividef(1.f, sum);
            #pragma unroll
            for (int j2 = 0; j2 < 8; ++j2) att[j2*DSTR + tid] = e[j2]*inv + EPSA;
        } else if (r < pad8) {
            #pragma unroll
            for (int j2 = 0; j2 < 8; ++j2) att[j2*DSTR + tid] = 0.f;
        }
    }
    __syncthreads();

    float P[16];
    #pragma unroll
    for (int i = 0; i < 16; ++i) P[i] = 0.f;
    float S = 0.f;
    #pragma unroll
    for (int s = 0; s < 4; ++s) {
        int nit = (cnts[s] + 7) >> 3;
        const __half* vb = g_vh + ((size_t)(b*(N/TILE_R) + chunk*4 + s) * TILE_R) * 64;
        #pragma unroll 2
        for (int it = 0; it < nit; ++it) {
            int r = it*8 + warp;
            float a = att[jj*DSTR + s*64 + r];
            S += a;
            const uint4* vp = (const uint4*)(vb + r*64) + gg*2;
            uint4 u0 = vp[0], u1 = vp[1];
            const __half2* h0 = reinterpret_cast<const __half2*>(&u0);
            const __half2* h1 = reinterpret_cast<const __half2*>(&u1);
            #pragma unroll
            for (int i = 0; i < 4; ++i) {
                float2 f = __half22float2(h0[i]);
                P[2*i]   += a*f.x;
                P[2*i+1] += a*f.y;
            }
            #pragma unroll
            for (int i = 0; i < 4; ++i) {
                float2 f = __half22float2(h1[i]);
                P[8+2*i]   += a*f.x;
                P[8+2*i+1] += a*f.y;
            }
        }
    }

    float* rp = redP + warp*512 + jj*64 + (gg << 4);
    #pragma unroll
    for (int i = 0; i < 4; ++i)
        *(float4*)(rp + 4*i) = make_float4(P[4*i], P[4*i+1], P[4*i+2], P[4*i+3]);
    if (gg == 0) redS[warp*8 + jj] = S;
    __syncthreads();

    #pragma unroll
    for (int u = 0; u < 2; ++u) {
        int t = tid + 256*u;
        float s = 0.f;
        #pragma unroll
        for (int w = 0; w < 8; ++w) s += redP[w*512 + t];
        g_Pp[((size_t)b*NB + chunk)*512 + t] = s;
    }
    if (tid < 8) {
        float s = 0.f;
        #pragma unroll
        for (int w = 0; w < 8; ++w) s += redS[w*8 + tid];
        g_Sp[(b*NB + chunk)*8 + tid] = s;
    }
}

// ---------------- slot update: explicit load-batching, high reg budget ----------------
__global__ __launch_bounds__(256, 2)
void k_update(const float* __restrict__ b_ih, const float* __restrict__ b_hh,
              const float* __restrict__ b1, const float* __restrict__ b2,
              const float* __restrict__ ln_ff_w, const float* __restrict__ ln_ff_b,
              const float* __restrict__ ln_s_w, const float* __restrict__ ln_s_b,
              const float* __restrict__ bq,
              float* __restrict__ d_out, int last) {
    __shared__ float upd[256], prev[256], snew[256], ffs[256], hid[512], sfin[256], Ssm[4];
    int b = blockIdx.y, half = blockIdx.x, tid = threadIdx.x;
    int j0 = half * 4;
    int j = tid >> 6, dd = tid & 63;
    int J = j0 + j;

    if (tid < 4) {
        float v[NB];
        const float* sp = g_Sp + b*NB*8 + j0 + tid;
        #pragma unroll
        for (int p = 0; p < NB; ++p) v[p] = sp[p*8];
        float s = 0.f;
        #pragma unroll
        for (int p = 0; p < NB; ++p) s += v[p];
        Ssm[tid] = s;
    }
    float pr;
    {
        float v[NB];
        const float* pp = g_Pp + (size_t)b*NB*512 + J*64 + dd;
        #pragma unroll
        for (int p = 0; p < NB; ++p) v[p] = pp[p*512];
        float s = 0.f;
        #pragma unroll
        for (int p = 0; p < NB; ++p) s += v[p];
        pr = s;
        prev[tid] = g_slots[b*512 + J*64 + dd];
    }
    __syncthreads();
    upd[tid] = pr / Ssm[j];
    __syncthreads();

    // GRU: explicit 8-wide load batches (wa 4 floats + wb 2 floats per d)
    {
        const float* uj = upd + j*64;
        const float* hj = prev + j*64;
        float xr = b_ih[dd], xz = b_ih[64+dd], xn = b_ih[128+dd];
        float hr = b_hh[dd], hz = b_hh[64+dd], hn = b_hh[128+dd];
        #pragma unroll
        for (int db = 0; db < 64; db += 8) {
            float4 wa8[8];
            float2 wb8[8];
            #pragma unroll
            for (int t = 0; t < 8; ++t) wa8[t] = __ldg(g_WgA + (db+t)*64 + dd);
            #pragma unroll
            for (int t = 0; t < 8; ++t) wb8[t] = __ldg(g_WgB + (db+t)*64 + dd);
            #pragma unroll
            for (int t = 0; t < 8; ++t) {
                float uu = uj[db+t], hh = hj[db+t];
                xr += uu*wa8[t].x; xz += uu*wa8[t].y; xn += uu*wa8[t].z;
                hr += hh*wa8[t].w; hz += hh*wb8[t].x; hn += hh*wb8[t].y;
            }
        }
        float rg = 1.f/(1.f + __expf(-(xr + hr)));
        float zg = 1.f/(1.f + __expf(-(xz + hz)));
        float t2 = __expf(2.f*(xn + rg*hn));
        float nn = 1.f - 2.f/(t2 + 1.f);
        snew[tid] = (1.f - zg)*nn + zg*prev[tid];
    }
    __syncthreads();
    lnrows(snew, ffs, ln_ff_w, ln_ff_b, tid, 4);
    __syncthreads();
    // MLP layer 1: explicit 16-wide batches
    {
        int h2 = dd;
        float a0 = b1[2*h2], a1 = b1[2*h2+1];
        const float* fj = ffs + j*64;
        #pragma unroll
        for (int db = 0; db < 64; db += 16) {
            float2 w8[16];
            #pragma unroll
            for (int t = 0; t < 16; ++t) w8[t] = __ldg(g_W1p + (db+t)*64 + h2);
            #pragma unroll
            for (int t = 0; t < 16; ++t) {
                float f = fj[db+t];
                a0 += f*w8[t].x; a1 += f*w8[t].y;
            }
        }
        hid[j*128 + 2*h2]   = fmaxf(a0, 0.f);
        hid[j*128 + 2*h2+1] = fmaxf(a1, 0.f);
    }
    __syncthreads();
    // MLP layer 2: explicit 16-wide batches
    {
        float acc = b2[dd];
        const float2* hj2 = (const float2*)(hid + j*128);
        #pragma unroll
        for (int hb = 0; hb < 64; hb += 16) {
            float2 w8[16];
            #pragma unroll
            for (int t = 0; t < 16; ++t) w8[t] = __ldg(g_W2p + (hb+t)*64 + dd);
            #pragma unroll
            for (int t = 0; t < 16; ++t) {
                float2 hv = hj2[hb+t];
                acc += hv.x*w8[t].x + hv.y*w8[t].y;
            }
        }
        float o = snew[tid] + acc;
        sfin[tid] = o;
        g_slots[b*512 + J*64 + dd] = o;
        if (last) d_out[b*512 + J*64 + dd] = o;
    }
    if (!last) {
        __syncthreads();
        lnrows(sfin, ffs, ln_s_w, ln_s_b, tid, 4);
        __syncthreads();
        {
            float acc = bq[dd];
            const float2* sj2 = (const float2*)(ffs + j*64);
            #pragma unroll
            for (int db = 0; db < 32; db += 16) {
                float2 w8[16];
                #pragma unroll
                for (int t = 0; t < 16; ++t) w8[t] = __ldg(g_Wqp + (db+t)*64 + dd);
                #pragma unroll
                for (int t = 0; t < 16; ++t) {
                    float2 s2 = sj2[db+t];
                    acc += s2.x*w8[t].x + s2.y*w8[t].y;
                }
            }
            g_q[b*512 + J*64 + dd] = acc * SCALE;
        }
    }
}

// ---------------- launch ----------------
extern "C" void kernel_launch(void* const* d_in, const int* in_sizes, int n_in,
                              void* d_out, int out_size) {
    const float* inputs     = (const float*)d_in[0];
    const int*   mask       = (const int*)  d_in[1];
    const float* noise      = (const float*)d_in[2];
    const float* slots_mu   = (const float*)d_in[3];
    const float* slots_sig  = (const float*)d_in[4];
    const float* Wq         = (const float*)d_in[5];
    const float* bq         = (const float*)d_in[6];
    const float* Wk         = (const float*)d_in[7];
    const float* bk         = (const float*)d_in[8];
    const float* Wv         = (const float*)d_in[9];
    const float* bv         = (const float*)d_in[10];
    const float* W_ih       = (const float*)d_in[11];
    const float* b_ih       = (const float*)d_in[12];
    const float* W_hh       = (const float*)d_in[13];
    const float* b_hh       = (const float*)d_in[14];
    const float* W1         = (const float*)d_in[15];
    const float* b1         = (const float*)d_in[16];
    const float* W2         = (const float*)d_in[17];
    const float* b2         = (const float*)d_in[18];
    const float* ln_in_w    = (const float*)d_in[19];
    const float* ln_in_b    = (const float*)d_in[20];
    const float* ln_s_w     = (const float*)d_in[21];
    const float* ln_s_b     = (const float*)d_in[22];
    const float* ln_ff_w    = (const float*)d_in[23];
    const float* ln_ff_b    = (const float*)d_in[24];
    float* out = (float*)d_out;

    k_prep_init<<<64, 256>>>(Wk, Wv, W_ih, W_hh, W1, W2, Wq,
                             noise, slots_mu, slots_sig, ln_s_w, ln_s_b, bq);
    k_ln_kv<<<(B*N)/TILE_R, 256>>>(inputs, mask, bk, bv, ln_in_w, ln_in_b);
    for (int it = 0; it < ITERS; ++it) {
        k_attn<<<dim3(NB, B), 256>>>();
        k_update<<<dim3(2, B), 256>>>(b_ih, b_hh, b1, b2, ln_ff_w, ln_ff_b,
                                      ln_s_w, ln_s_b, bq, out, it == ITERS-1 ? 1 : 0);
    }
}

// round 14
// speedup vs baseline: 2.1400x; 1.1552x over previous
#include <cuda_runtime.h>
#include <cuda_fp16.h>
#include <cstdint>

// ---------------- problem constants ----------------
#define B       64
#define N       4096
#define H       128
#define NS      8
#define ITERS   3
#define EPSA    1e-8f
#define LN_EPS  1e-5f
#define SCALE   0.125f

#define TILE_R  64
#define NB      16
#define DSTR    257
#define QSTR    66
#define WSTR    66              // padded stride for fp16 weight smem

typedef unsigned long long ull;

// ---------------- device scratch ----------------
__device__ __half g_kh[B*N*64];
__device__ __half g_vh[B*N*64];
__device__ int    g_cnt[B*N/TILE_R];
__device__ float  g_slots[B*NS*64];
__device__ float  g_q[B*NS*64];
__device__ float  g_Pp[B*NB*NS*64];
__device__ float  g_Sp[B*NB*NS];
__device__ __half g_wkh[64*64];        // [c][d] fp16
__device__ __half g_wvh[64*64];
__device__ float4 g_WgA[64*64];        // [d][dd] = (Wih_r, Wih_z, Wih_n, Whh_r)
__device__ float2 g_WgB[64*64];        // [d][dd] = (Whh_z, Whh_n)
__device__ float2 g_W1p[64*64];        // [d][h2]
__device__ float2 g_W2p[64*64];        // [h2][dd]
__device__ float2 g_Wqp[32*64];        // [d2][dd]

// ---------------- helpers ----------------
__device__ __forceinline__ uint32_t smem_u32(const void* p) {
    uint32_t a;
    asm("{ .reg .u64 t; cvta.to.shared.u64 t, %1; cvt.u32.u64 %0, t; }" : "=r"(a) : "l"(p));
    return a;
}

// ---------------- merged prep + init ----------------
__global__ __launch_bounds__(256)
void k_prep_init(const float* __restrict__ Wk, const float* __restrict__ Wv,
                 const float* __restrict__ W_ih, const float* __restrict__ W_hh,
                 const float* __restrict__ W1, const float* __restrict__ W2,
                 const float* __restrict__ Wq,
                 const float* __restrict__ noise, const float* __restrict__ mu,
                 const float* __restrict__ sg,
                 const float* __restrict__ ln_s_w, const float* __restrict__ ln_s_b,
                 const float* __restrict__ bq) {
    int tid = threadIdx.x;
    int i = blockIdx.x * 256 + tid;
    if (i < 4096) {
        // fp16 weights for HMMA kv projection
        g_wkh[i] = __float2half_rn(Wk[i]);
        g_wvh[i] = __float2half_rn(Wv[i]);
        int d = i >> 6, x = i & 63;
        g_WgA[i] = make_float4(W_ih[x*64 + d], W_ih[(64+x)*64 + d],
                               W_ih[(128+x)*64 + d], W_hh[x*64 + d]);
        g_WgB[i] = make_float2(W_hh[(64+x)*64 + d], W_hh[(128+x)*64 + d]);
        g_W1p[i] = make_float2(W1[(2*x)*64 + d], W1[(2*x+1)*64 + d]);
        g_W2p[i] = make_float2(W2[x*128 + 2*d], W2[x*128 + 2*d + 1]);
    }
    if (i < 2048) {
        int d2 = i >> 6, dd = i & 63;
        g_Wqp[i] = make_float2(Wq[dd*64 + 2*d2], Wq[dd*64 + 2*d2 + 1]);
    }
    // init slots + LN + q0
    __shared__ float sl[512], sn[512];
    int b = blockIdx.x;
    #pragma unroll
    for (int u = 0; u < 2; ++u) {
        int t = tid + 256*u, dd = t & 63;
        float s = mu[dd] + sg[dd]*noise[b*512 + t];
        sl[t] = s;
        g_slots[b*512 + t] = s;
    }
    __syncthreads();
    {
        int wp = tid >> 5, lane = tid & 31;
        const float* p = sl + wp*64;
        float v0 = p[lane], v1 = p[lane+32];
        float s = v0 + v1;
        #pragma unroll
        for (int o = 16; o; o >>= 1) s += __shfl_xor_sync(~0u, s, o);
        float mmu = s * (1.f/64.f);
        float d0 = v0 - mmu, d1 = v1 - mmu;
        float q = d0*d0 + d1*d1;
        #pragma unroll
        for (int o = 16; o; o >>= 1) q += __shfl_xor_sync(~0u, q, o);
        float rs = rsqrtf(q * (1.f/64.f) + LN_EPS);
        sn[wp*64 + lane]      = d0*rs*ln_s_w[lane] + ln_s_b[lane];
        sn[wp*64 + lane + 32] = d1*rs*ln_s_w[lane+32] + ln_s_b[lane+32];
    }
    __syncthreads();
    #pragma unroll
    for (int u = 0; u < 2; ++u) {
        int t = tid + 256*u, j = t >> 6, dd = t & 63;
        float acc = bq[dd];
        const float2* sj2 = (const float2*)(sn + j*64);
        #pragma unroll 8
        for (int d2 = 0; d2 < 32; ++d2) {
            float2 w = *(const float2*)(Wq + dd*64 + 2*d2);
            float2 s2 = sj2[d2];
            acc += s2.x*w.x + s2.y*w.y;
        }
        g_q[b*512 + t] = acc * SCALE;
    }
}

// ---------------- K1: mask-compact + shuffle-free LN + HMMA k/v GEMM ----------------
__global__ __launch_bounds__(256)
void k_ln_kv(const float* __restrict__ inputs, const int* __restrict__ mask,
             const float* __restrict__ bk, const float* __restrict__ bv,
             const float* __restrict__ lnw, const float* __restrict__ lnb) {
    __shared__ __align__(16) float xs[TILE_R*64];       // 16KB fp32 LN'd rows
    __shared__ __align__(16) char  xh[TILE_R*128];      // 8KB fp16 swizzled tile
    __shared__ __align__(4) __half wk[64*WSTR];         // fp16 Wk [c][WSTR]
    __shared__ __align__(4) __half wv[64*WSTR];
    __shared__ float ps[TILE_R*4], pq[TILE_R*4];
    __shared__ float rmu[TILE_R], rrs[TILE_R];
    __shared__ int tpos[TILE_R];
    __shared__ int cmap[TILE_R];
    __shared__ int wc[2];

    int tid = threadIdx.x;
    int lane = tid & 31, warp = tid >> 5;
    size_t row0 = (size_t)blockIdx.x * TILE_R;

    // stage fp16 weights
    for (int i = tid; i < 4096; i += 256) {
        int c = i >> 6, d = i & 63;
        wk[c*WSTR + d] = g_wkh[i];
        wv[c*WSTR + d] = g_wvh[i];
    }

    if (tid < 64) {
        int mm = mask[row0 + tid] != 0;
        unsigned bal = __ballot_sync(~0u, mm);
        if (lane == 0) wc[warp] = __popc(bal);
        tpos[tid] = mm ? __popc(bal & ((1u << lane) - 1u)) : -1;
    }
    __syncthreads();
    int act = wc[0] + wc[1];
    if (tid < 64 && tpos[tid] >= 0)
        cmap[tpos[tid] + (tid >= 32 ? wc[0] : 0)] = tid;
    if (tid == 0) g_cnt[blockIdx.x] = act;
    __syncthreads();

    // LN-a: gather active rows coalesced
    {
        int rph = tid >> 4;
        int quad = tid & 15;
        for (int base = 0; base < act; base += 16) {
            int ci = base + rph;
            if (ci < act) {
                int r = cmap[ci];
                *(float4*)(xs + ci*64 + quad*4) =
                    *(const float4*)(inputs + (row0 + r)*64 + quad*4);
            }
        }
    }
    __syncthreads();

    // LN-b: per-(row, quarter) partials
    {
        int ci = tid >> 2, q = tid & 3;
        if (ci < act) {
            const float4* p = (const float4*)(xs + ci*64 + q*16);
            float s = 0.f, ss = 0.f;
            #pragma unroll
            for (int i = 0; i < 4; ++i) {
                float4 v = p[i];
                s  += (v.x + v.y) + (v.z + v.w);
                ss += (v.x*v.x + v.y*v.y) + (v.z*v.z + v.w*v.w);
            }
            ps[ci*4 + q] = s;
            pq[ci*4 + q] = ss;
        }
    }
    __syncthreads();

    if (tid < act) {
        float s  = (ps[tid*4] + ps[tid*4+1]) + (ps[tid*4+2] + ps[tid*4+3]);
        float ss = (pq[tid*4] + pq[tid*4+1]) + (pq[tid*4+2] + pq[tid*4+3]);
        float mu  = s * (1.f/64.f);
        float var = ss * (1.f/64.f) - mu*mu;
        rmu[tid] = mu;
        rrs[tid] = rsqrtf(var + LN_EPS);
    }
    __syncthreads();

    // LN-d+e: normalize and convert to swizzled fp16 tile (8 halves per thread-step)
    {
        int tot = act * 8;           // uint4 (8 halves) units
        for (int e = tid; e < tot; e += 256) {
            int ci = e >> 3, q = e & 7;        // q = 16-byte group
            float mu = rmu[ci], rs = rrs[ci];
            float4 v0 = *(float4*)(xs + ci*64 + q*8);
            float4 v1 = *(float4*)(xs + ci*64 + q*8 + 4);
            float4 w0 = __ldg((const float4*)lnw + 2*q);
            float4 w1 = __ldg((const float4*)lnw + 2*q + 1);
            float4 b0 = __ldg((const float4*)lnb + 2*q);
            float4 b1 = __ldg((const float4*)lnb + 2*q + 1);
            __half2 h[4];
            h[0] = __floats2half2_rn((v0.x - mu)*rs*w0.x + b0.x, (v0.y - mu)*rs*w0.y + b0.y);
            h[1] = __floats2half2_rn((v0.z - mu)*rs*w0.z + b0.z, (v0.w - mu)*rs*w0.w + b0.w);
            h[2] = __floats2half2_rn((v1.x - mu)*rs*w1.x + b1.x, (v1.y - mu)*rs*w1.y + b1.y);
            h[3] = __floats2half2_rn((v1.z - mu)*rs*w1.z + b1.z, (v1.w - mu)*rs*w1.w + b1.w);
            *(uint4*)(xh + ci*128 + ((q ^ (ci & 7)) << 4)) = *(uint4*)h;
        }
    }
    __syncthreads();

    // HMMA GEMM: warps 0-3 -> k, warps 4-7 -> v; each warp: 2 n-tiles x 4 m-tiles
    {
        int wsel = warp >> 2;                       // 0 = k, 1 = v
        int n0 = (warp & 3) * 16;                   // two n-tiles: n0, n0+8
        const __half* wh = wsel ? wv : wk;
        const float*  bias = wsel ? bv : bk;
        __half* dst = wsel ? g_vh : g_kh;

        uint32_t xh_base = smem_u32(xh);
        int j = lane >> 2, kb = (lane & 3) * 2;
        float acc[2][4][4];
        #pragma unroll
        for (int ns = 0; ns < 2; ++ns)
            #pragma unroll
            for (int mt = 0; mt < 4; ++mt)
                #pragma unroll
                for (int i = 0; i < 4; ++i) acc[ns][mt][i] = 0.f;

        #pragma unroll
        for (int ks = 0; ks < 4; ++ks) {
            uint32_t b0a = *(const uint32_t*)(wh + (n0 + j)*WSTR + 16*ks + kb);
            uint32_t b1a = *(const uint32_t*)(wh + (n0 + j)*WSTR + 16*ks + kb + 8);
            uint32_t b0b = *(const uint32_t*)(wh + (n0 + 8 + j)*WSTR + 16*ks + kb);
            uint32_t b1b = *(const uint32_t*)(wh + (n0 + 8 + j)*WSTR + 16*ks + kb + 8);
            #pragma unroll
            for (int mt = 0; mt < 4; ++mt) {
                int lr = mt*16 + (lane & 15);
                int qq = 2*ks + (lane >> 4);
                uint32_t addr = xh_base + lr*128 + ((qq ^ (lr & 7)) << 4);
                uint32_t a0, a1, a2, a3;
                asm volatile("ldmatrix.sync.aligned.m8n8.x4.shared.b16 {%0,%1,%2,%3}, [%4];"
                             : "=r"(a0), "=r"(a1), "=r"(a2), "=r"(a3) : "r"(addr));
                asm volatile("mma.sync.aligned.m16n8k16.row.col.f32.f16.f16.f32 "
                             "{%0,%1,%2,%3}, {%4,%5,%6,%7}, {%8,%9}, {%0,%1,%2,%3};"
                             : "+f"(acc[0][mt][0]), "+f"(acc[0][mt][1]),
                               "+f"(acc[0][mt][2]), "+f"(acc[0][mt][3])
                             : "r"(a0), "r"(a1), "r"(a2), "r"(a3), "r"(b0a), "r"(b1a));
                asm volatile("mma.sync.aligned.m16n8k16.row.col.f32.f16.f16.f32 "
                             "{%0,%1,%2,%3}, {%4,%5,%6,%7}, {%8,%9}, {%0,%1,%2,%3};"
                             : "+f"(acc[1][mt][0]), "+f"(acc[1][mt][1]),
                               "+f"(acc[1][mt][2]), "+f"(acc[1][mt][3])
                             : "r"(a0), "r"(a1), "r"(a2), "r"(a3), "r"(b0b), "r"(b1b));
            }
        }

        // store with bias; rows >= act discarded (keeps zero padding invariant)
        int trow = lane >> 2;
        #pragma unroll
        for (int ns = 0; ns < 2; ++ns) {
            int c = n0 + ns*8 + (lane & 3)*2;
            float bx = __ldg(bias + c), by = __ldg(bias + c + 1);
            #pragma unroll
            for (int mt = 0; mt < 4; ++mt) {
                int r0 = mt*16 + trow;
                int r1 = r0 + 8;
                if (r0 < act) {
                    __half2 hv = __floats2half2_rn(acc[ns][mt][0] + bx, acc[ns][mt][1] + by);
                    *(__half2*)(dst + (row0 + r0)*64 + c) = hv;
                }
                if (r1 < act) {
                    __half2 hv = __floats2half2_rn(acc[ns][mt][2] + bx, acc[ns][mt][3] + by);
                    *(__half2*)(dst + (row0 + r1)*64 + c) = hv;
                }
            }
        }
    }
}

// ---------------- LN over slot rows ----------------
__device__ __forceinline__ void lnrows(const float* in, float* out,
                                       const float* __restrict__ w,
                                       const float* __restrict__ bia, int tid, int nrows) {
    int wp = tid >> 5, lane = tid & 31;
    if (wp >= nrows) return;
    const float* p = in + wp*64;
    float v0 = p[lane], v1 = p[lane+32];
    float s = v0 + v1;
    #pragma unroll
    for (int o = 16; o; o >>= 1) s += __shfl_xor_sync(~0u, s, o);
    float mu = s * (1.f/64.f);
    float d0 = v0 - mu, d1 = v1 - mu;
    float q = d0*d0 + d1*d1;
    #pragma unroll
    for (int o = 16; o; o >>= 1) q += __shfl_xor_sync(~0u, q, o);
    float rs = rsqrtf(q * (1.f/64.f) + LN_EPS);
    out[wp*64 + lane]      = d0*rs*w[lane] + bia[lane];
    out[wp*64 + lane + 32] = d1*rs*w[lane+32] + bia[lane+32];
}

// ---------------- attention: HMMA phase A + scalar phase C (R12 proven) ----------------
__global__ __launch_bounds__(256)
void k_attn() {
    __shared__ __align__(16) char sbuf[32*1024];
    __shared__ __align__(16) float dots[8*DSTR];
    __shared__ __align__(4)  __half qh[8*QSTR];
    __shared__ int cnts[4];

    __half* stg  = (__half*)sbuf;
    float*  att  = (float*)sbuf;
    float*  redP = (float*)(sbuf + 8*DSTR*sizeof(float));
    float*  redS = redP + 4096;

    int b = blockIdx.y, chunk = blockIdx.x;
    int tid = threadIdx.x;
    int warp = tid >> 5, lane = tid & 31;
    int jj = lane & 7;
    int gg = lane >> 3;

    if (tid < 4) cnts[tid] = g_cnt[b*(N/TILE_R) + chunk*4 + tid];

    {
        const uint4* src = (const uint4*)(g_kh + ((size_t)b*N + chunk*256)*64);
        #pragma unroll
        for (int e0 = 0; e0 < 2048; e0 += 256) {
            int e = e0 + tid;
            int ci = e >> 3, q = e & 7;
            uint4 v = __ldg(src + e);
            *(uint4*)(sbuf + ci*128 + ((q ^ (ci & 7)) << 4)) = v;
        }
    }
    for (int e = tid; e < 512; e += 256) {
        int j = e >> 6, d = e & 63;
        qh[j*QSTR + d] = __float2half_rn(g_q[b*512 + e]);
    }
    __syncthreads();

    {
        uint32_t stg_base = smem_u32(stg);
        int R0 = warp * 32;
        float d0[4] = {0.f,0.f,0.f,0.f};
        float d1[4] = {0.f,0.f,0.f,0.f};
        int j = lane >> 2, kb = (lane & 3) * 2;
        #pragma unroll
        for (int ks = 0; ks < 4; ++ks) {
            uint32_t b0 = *(const uint32_t*)(qh + j*QSTR + 16*ks + kb);
            uint32_t b1 = *(const uint32_t*)(qh + j*QSTR + 16*ks + kb + 8);
            #pragma unroll
            for (int tile = 0; tile < 2; ++tile) {
                int lr = R0 + tile*16 + (lane & 15);
                int qq = 2*ks + (lane >> 4);
                uint32_t addr = stg_base + lr*128 + ((qq ^ (lr & 7)) << 4);
                uint32_t a0, a1, a2, a3;
                asm volatile("ldmatrix.sync.aligned.m8n8.x4.shared.b16 {%0,%1,%2,%3}, [%4];"
                             : "=r"(a0), "=r"(a1), "=r"(a2), "=r"(a3) : "r"(addr));
                float* dd = tile ? d1 : d0;
                asm volatile("mma.sync.aligned.m16n8k16.row.col.f32.f16.f16.f32 "
                             "{%0,%1,%2,%3}, {%4,%5,%6,%7}, {%8,%9}, {%0,%1,%2,%3};"
                             : "+f"(dd[0]), "+f"(dd[1]), "+f"(dd[2]), "+f"(dd[3])
                             : "r"(a0), "r"(a1), "r"(a2), "r"(a3), "r"(b0), "r"(b1));
            }
        }
        int s = warp >> 1;
        int rbase = (warp & 1) * 32;
        int trow = lane >> 2;
        int col = (lane & 3) * 2;
        #pragma unroll
        for (int tile = 0; tile < 2; ++tile) {
            float* dd = tile ? d1 : d0;
            int r = rbase + tile*16 + trow;
            dots[(col  )*DSTR + s*64 + r    ] = dd[0];
            dots[(col+1)*DSTR + s*64 + r    ] = dd[1];
            dots[(col  )*DSTR + s*64 + r + 8] = dd[2];
            dots[(col+1)*DSTR + s*64 + r + 8] = dd[3];
        }
    }
    __syncthreads();

    {
        int s = tid >> 6, r = tid & 63;
        int act = cnts[s];
        int pad8 = (act + 7) & ~7;
        if (r < act) {
            float d[8];
            #pragma unroll
            for (int j2 = 0; j2 < 8; ++j2) d[j2] = dots[j2*DSTR + tid];
            float m = d[0];
            #pragma unroll
            for (int j2 = 1; j2 < 8; ++j2) m = fmaxf(m, d[j2]);
            float e[8], sum = 0.f;
            #pragma unroll
            for (int j2 = 0; j2 < 8; ++j2) { e[j2] = __expf(d[j2] - m); sum += e[j2]; }
            float inv = __fdividef(1.f, sum);
            #pragma unroll
            for (int j2 = 0; j2 < 8; ++j2) att[j2*DSTR + tid] = e[j2]*inv + EPSA;
        } else if (r < pad8) {
            #pragma unroll
            for (int j2 = 0; j2 < 8; ++j2) att[j2*DSTR + tid] = 0.f;
        }
    }
    __syncthreads();

    float P[16];
    #pragma unroll
    for (int i = 0; i < 16; ++i) P[i] = 0.f;
    float S = 0.f;
    #pragma unroll
    for (int s = 0; s < 4; ++s) {
        int nit = (cnts[s] + 7) >> 3;
        const __half* vb = g_vh + ((size_t)(b*(N/TILE_R) + chunk*4 + s) * TILE_R) * 64;
        #pragma unroll 2
        for (int it = 0; it < nit; ++it) {
            int r = it*8 + warp;
            float a = att[jj*DSTR + s*64 + r];
            S += a;
            const uint4* vp = (const uint4*)(vb + r*64) + gg*2;
            uint4 u0 = vp[0], u1 = vp[1];
            const __half2* h0 = reinterpret_cast<const __half2*>(&u0);
            const __half2* h1 = reinterpret_cast<const __half2*>(&u1);
            #pragma unroll
            for (int i = 0; i < 4; ++i) {
                float2 f = __half22float2(h0[i]);
                P[2*i]   += a*f.x;
                P[2*i+1] += a*f.y;
            }
            #pragma unroll
            for (int i = 0; i < 4; ++i) {
                float2 f = __half22float2(h1[i]);
                P[8+2*i]   += a*f.x;
                P[8+2*i+1] += a*f.y;
            }
        }
    }

    float* rp = redP + warp*512 + jj*64 + (gg << 4);
    #pragma unroll
    for (int i = 0; i < 4; ++i)
        *(float4*)(rp + 4*i) = make_float4(P[4*i], P[4*i+1], P[4*i+2], P[4*i+3]);
    if (gg == 0) redS[warp*8 + jj] = S;
    __syncthreads();

    #pragma unroll
    for (int u = 0; u < 2; ++u) {
        int t = tid + 256*u;
        float s = 0.f;
        #pragma unroll
        for (int w = 0; w < 8; ++w) s += redP[w*512 + t];
        g_Pp[((size_t)b*NB + chunk)*512 + t] = s;
    }
    if (tid < 8) {
        float s = 0.f;
        #pragma unroll
        for (int w = 0; w < 8; ++w) s += redS[w*8 + tid];
        g_Sp[(b*NB + chunk)*8 + tid] = s;
    }
}

// ---------------- slot update: explicit load-batching (R13 proven) ----------------
__global__ __launch_bounds__(256, 2)
void k_update(const float* __restrict__ b_ih, const float* __restrict__ b_hh,
              const float* __restrict__ b1, const float* __restrict__ b2,
              const float* __restrict__ ln_ff_w, const float* __restrict__ ln_ff_b,
              const float* __restrict__ ln_s_w, const float* __restrict__ ln_s_b,
              const float* __restrict__ bq,
              float* __restrict__ d_out, int last) {
    __shared__ float upd[256], prev[256], snew[256], ffs[256], hid[512], sfin[256], Ssm[4];
    int b = blockIdx.y, half = blockIdx.x, tid = threadIdx.x;
    int j0 = half * 4;
    int j = tid >> 6, dd = tid & 63;
    int J = j0 + j;

    if (tid < 4) {
        float v[NB];
        const float* sp = g_Sp + b*NB*8 + j0 + tid;
        #pragma unroll
        for (int p = 0; p < NB; ++p) v[p] = sp[p*8];
        float s = 0.f;
        #pragma unroll
        for (int p = 0; p < NB; ++p) s += v[p];
        Ssm[tid] = s;
    }
    float pr;
    {
        float v[NB];
        const float* pp = g_Pp + (size_t)b*NB*512 + J*64 + dd;
        #pragma unroll
        for (int p = 0; p < NB; ++p) v[p] = pp[p*512];
        float s = 0.f;
        #pragma unroll
        for (int p = 0; p < NB; ++p) s += v[p];
        pr = s;
        prev[tid] = g_slots[b*512 + J*64 + dd];
    }
    __syncthreads();
    upd[tid] = pr / Ssm[j];
    __syncthreads();

    {
        const float* uj = upd + j*64;
        const float* hj = prev + j*64;
        float xr = b_ih[dd], xz = b_ih[64+dd], xn = b_ih[128+dd];
        float hr = b_hh[dd], hz = b_hh[64+dd], hn = b_hh[128+dd];
        #pragma unroll
        for (int db = 0; db < 64; db += 8) {
            float4 wa8[8];
            float2 wb8[8];
            #pragma unroll
            for (int t = 0; t < 8; ++t) wa8[t] = __ldg(g_WgA + (db+t)*64 + dd);
            #pragma unroll
            for (int t = 0; t < 8; ++t) wb8[t] = __ldg(g_WgB + (db+t)*64 + dd);
            #pragma unroll
            for (int t = 0; t < 8; ++t) {
                float uu = uj[db+t], hh = hj[db+t];
                xr += uu*wa8[t].x; xz += uu*wa8[t].y; xn += uu*wa8[t].z;
                hr += hh*wa8[t].w; hz += hh*wb8[t].x; hn += hh*wb8[t].y;
            }
        }
        float rg = 1.f/(1.f + __expf(-(xr + hr)));
        float zg = 1.f/(1.f + __expf(-(xz + hz)));
        float t2 = __expf(2.f*(xn + rg*hn));
        float nn = 1.f - 2.f/(t2 + 1.f);
        snew[tid] = (1.f - zg)*nn + zg*prev[tid];
    }
    __syncthreads();
    lnrows(snew, ffs, ln_ff_w, ln_ff_b, tid, 4);
    __syncthreads();
    {
        int h2 = dd;
        float a0 = b1[2*h2], a1 = b1[2*h2+1];
        const float* fj = ffs + j*64;
        #pragma unroll
        for (int db = 0; db < 64; db += 16) {
            float2 w8[16];
            #pragma unroll
            for (int t = 0; t < 16; ++t) w8[t] = __ldg(g_W1p + (db+t)*64 + h2);
            #pragma unroll
            for (int t = 0; t < 16; ++t) {
                float f = fj[db+t];
                a0 += f*w8[t].x; a1 += f*w8[t].y;
            }
        }
        hid[j*128 + 2*h2]   = fmaxf(a0, 0.f);
        hid[j*128 + 2*h2+1] = fmaxf(a1, 0.f);
    }
    __syncthreads();
    {
        float acc = b2[dd];
        const float2* hj2 = (const float2*)(hid + j*128);
        #pragma unroll
        for (int hb = 0; hb < 64; hb += 16) {
            float2 w8[16];
            #pragma unroll
            for (int t = 0; t < 16; ++t) w8[t] = __ldg(g_W2p + (hb+t)*64 + dd);
            #pragma unroll
            for (int t = 0; t < 16; ++t) {
                float2 hv = hj2[hb+t];
                acc += hv.x*w8[t].x + hv.y*w8[t].y;
            }
        }
        float o = snew[tid] + acc;
        sfin[tid] = o;
        g_slots[b*512 + J*64 + dd] = o;
        if (last) d_out[b*512 + J*64 + dd] = o;
    }
    if (!last) {
        __syncthreads();
        lnrows(sfin, ffs, ln_s_w, ln_s_b, tid, 4);
        __syncthreads();
        {
            float acc = bq[dd];
            const float2* sj2 = (const float2*)(ffs + j*64);
            #pragma unroll
            for (int db = 0; db < 32; db += 16) {
                float2 w8[16];
                #pragma unroll
                for (int t = 0; t < 16; ++t) w8[t] = __ldg(g_Wqp + (db+t)*64 + dd);
                #pragma unroll
                for (int t = 0; t < 16; ++t) {
                    float2 s2 = sj2[db+t];
                    acc += s2.x*w8[t].x + s2.y*w8[t].y;
                }
            }
            g_q[b*512 + J*64 + dd] = acc * SCALE;
        }
    }
}

// ---------------- launch ----------------
extern "C" void kernel_launch(void* const* d_in, const int* in_sizes, int n_in,
                              void* d_out, int out_size) {
    const float* inputs     = (const float*)d_in[0];
    const int*   mask       = (const int*)  d_in[1];
    const float* noise      = (const float*)d_in[2];
    const float* slots_mu   = (const float*)d_in[3];
    const float* slots_sig  = (const float*)d_in[4];
    const float* Wq         = (const float*)d_in[5];
    const float* bq         = (const float*)d_in[6];
    const float* Wk         = (const float*)d_in[7];
    const float* bk         = (const float*)d_in[8];
    const float* Wv         = (const float*)d_in[9];
    const float* bv         = (const float*)d_in[10];
    const float* W_ih       = (const float*)d_in[11];
    const float* b_ih       = (const float*)d_in[12];
    const float* W_hh       = (const float*)d_in[13];
    const float* b_hh       = (const float*)d_in[14];
    const float* W1         = (const float*)d_in[15];
    const float* b1         = (const float*)d_in[16];
    const float* W2         = (const float*)d_in[17];
    const float* b2         = (const float*)d_in[18];
    const float* ln_in_w    = (const float*)d_in[19];
    const float* ln_in_b    = (const float*)d_in[20];
    const float* ln_s_w     = (const float*)d_in[21];
    const float* ln_s_b     = (const float*)d_in[22];
    const float* ln_ff_w    = (const float*)d_in[23];
    const float* ln_ff_b    = (const float*)d_in[24];
    float* out = (float*)d_out;

    k_prep_init<<<64, 256>>>(Wk, Wv, W_ih, W_hh, W1, W2, Wq,
                             noise, slots_mu, slots_sig, ln_s_w, ln_s_b, bq);
    k_ln_kv<<<(B*N)/TILE_R, 256>>>(inputs, mask, bk, bv, ln_in_w, ln_in_b);
    for (int it = 0; it < ITERS; ++it) {
        k_attn<<<dim3(NB, B), 256>>>();
        k_update<<<dim3(2, B), 256>>>(b_ih, b_hh, b1, b2, ln_ff_w, ln_ff_b,
                                      ln_s_w, ln_s_b, bq, out, it == ITERS-1 ? 1 : 0);
    }
}

// round 15
// speedup vs baseline: 2.2885x; 1.0694x over previous
#include <cuda_runtime.h>
#include <cuda_fp16.h>
#include <cstdint>

// ---------------- problem constants ----------------
#define B       64
#define N       4096
#define H       128
#define NS      8
#define ITERS   3
#define EPSA    1e-8f
#define LN_EPS  1e-5f
#define SCALE   0.125f

#define TILE_R  64
#define NB      16
#define DSTR    257
#define QSTR    66
#define WSTR    66
#define ASTR    272             // fp16 att tile stride (halves)

typedef unsigned long long ull;

// ---------------- device scratch ----------------
__device__ __half g_kh[B*N*64];
__device__ __half g_vh[B*N*64];
__device__ int    g_cnt[B*N/TILE_R];
__device__ float  g_slots[B*NS*64];
__device__ float  g_q[B*NS*64];
__device__ float  g_Pp[B*NB*NS*64];
__device__ float  g_Sp[B*NB*NS];
__device__ __half g_wkh[64*64];        // [c][d] fp16
__device__ __half g_wvh[64*64];
__device__ float4 g_WgA[64*64];
__device__ float2 g_WgB[64*64];
__device__ float2 g_W1p[64*64];
__device__ float2 g_W2p[64*64];
__device__ float2 g_Wqp[32*64];

// ---------------- helpers ----------------
__device__ __forceinline__ uint32_t smem_u32(const void* p) {
    uint32_t a;
    asm("{ .reg .u64 t; cvta.to.shared.u64 t, %1; cvt.u32.u64 %0, t; }" : "=r"(a) : "l"(p));
    return a;
}

// ---------------- merged prep + init ----------------
__global__ __launch_bounds__(256)
void k_prep_init(const float* __restrict__ Wk, const float* __restrict__ Wv,
                 const float* __restrict__ W_ih, const float* __restrict__ W_hh,
                 const float* __restrict__ W1, const float* __restrict__ W2,
                 const float* __restrict__ Wq,
                 const float* __restrict__ noise, const float* __restrict__ mu,
                 const float* __restrict__ sg,
                 const float* __restrict__ ln_s_w, const float* __restrict__ ln_s_b,
                 const float* __restrict__ bq) {
    int tid = threadIdx.x;
    int i = blockIdx.x * 256 + tid;
    if (i < 4096) {
        g_wkh[i] = __float2half_rn(Wk[i]);
        g_wvh[i] = __float2half_rn(Wv[i]);
        int d = i >> 6, x = i & 63;
        g_WgA[i] = make_float4(W_ih[x*64 + d], W_ih[(64+x)*64 + d],
                               W_ih[(128+x)*64 + d], W_hh[x*64 + d]);
        g_WgB[i] = make_float2(W_hh[(64+x)*64 + d], W_hh[(128+x)*64 + d]);
        g_W1p[i] = make_float2(W1[(2*x)*64 + d], W1[(2*x+1)*64 + d]);
        g_W2p[i] = make_float2(W2[x*128 + 2*d], W2[x*128 + 2*d + 1]);
    }
    if (i < 2048) {
        int d2 = i >> 6, dd = i & 63;
        g_Wqp[i] = make_float2(Wq[dd*64 + 2*d2], Wq[dd*64 + 2*d2 + 1]);
    }
    __shared__ float sl[512], sn[512];
    int b = blockIdx.x;
    #pragma unroll
    for (int u = 0; u < 2; ++u) {
        int t = tid + 256*u, dd = t & 63;
        float s = mu[dd] + sg[dd]*noise[b*512 + t];
        sl[t] = s;
        g_slots[b*512 + t] = s;
    }
    __syncthreads();
    {
        int wp = tid >> 5, lane = tid & 31;
        const float* p = sl + wp*64;
        float v0 = p[lane], v1 = p[lane+32];
        float s = v0 + v1;
        #pragma unroll
        for (int o = 16; o; o >>= 1) s += __shfl_xor_sync(~0u, s, o);
        float mmu = s * (1.f/64.f);
        float d0 = v0 - mmu, d1 = v1 - mmu;
        float q = d0*d0 + d1*d1;
        #pragma unroll
        for (int o = 16; o; o >>= 1) q += __shfl_xor_sync(~0u, q, o);
        float rs = rsqrtf(q * (1.f/64.f) + LN_EPS);
        sn[wp*64 + lane]      = d0*rs*ln_s_w[lane] + ln_s_b[lane];
        sn[wp*64 + lane + 32] = d1*rs*ln_s_w[lane+32] + ln_s_b[lane+32];
    }
    __syncthreads();
    #pragma unroll
    for (int u = 0; u < 2; ++u) {
        int t = tid + 256*u, j = t >> 6, dd = t & 63;
        float acc = bq[dd];
        const float2* sj2 = (const float2*)(sn + j*64);
        #pragma unroll 8
        for (int d2 = 0; d2 < 32; ++d2) {
            float2 w = *(const float2*)(Wq + dd*64 + 2*d2);
            float2 s2 = sj2[d2];
            acc += s2.x*w.x + s2.y*w.y;
        }
        g_q[b*512 + t] = acc * SCALE;
    }
}

// ---------------- K1: mask-compact + shuffle-free LN + HMMA k/v GEMM (R14 proven) ----------------
__global__ __launch_bounds__(256)
void k_ln_kv(const float* __restrict__ inputs, const int* __restrict__ mask,
             const float* __restrict__ bk, const float* __restrict__ bv,
             const float* __restrict__ lnw, const float* __restrict__ lnb) {
    __shared__ __align__(16) float xs[TILE_R*64];
    __shared__ __align__(16) char  xh[TILE_R*128];
    __shared__ __align__(4) __half wk[64*WSTR];
    __shared__ __align__(4) __half wv[64*WSTR];
    __shared__ float ps[TILE_R*4], pq[TILE_R*4];
    __shared__ float rmu[TILE_R], rrs[TILE_R];
    __shared__ int tpos[TILE_R];
    __shared__ int cmap[TILE_R];
    __shared__ int wc[2];

    int tid = threadIdx.x;
    int lane = tid & 31, warp = tid >> 5;
    size_t row0 = (size_t)blockIdx.x * TILE_R;

    for (int i = tid; i < 4096; i += 256) {
        int c = i >> 6, d = i & 63;
        wk[c*WSTR + d] = g_wkh[i];
        wv[c*WSTR + d] = g_wvh[i];
    }

    if (tid < 64) {
        int mm = mask[row0 + tid] != 0;
        unsigned bal = __ballot_sync(~0u, mm);
        if (lane == 0) wc[warp] = __popc(bal);
        tpos[tid] = mm ? __popc(bal & ((1u << lane) - 1u)) : -1;
    }
    __syncthreads();
    int act = wc[0] + wc[1];
    if (tid < 64 && tpos[tid] >= 0)
        cmap[tpos[tid] + (tid >= 32 ? wc[0] : 0)] = tid;
    if (tid == 0) g_cnt[blockIdx.x] = act;
    __syncthreads();

    {
        int rph = tid >> 4;
        int quad = tid & 15;
        for (int base = 0; base < act; base += 16) {
            int ci = base + rph;
            if (ci < act) {
                int r = cmap[ci];
                *(float4*)(xs + ci*64 + quad*4) =
                    *(const float4*)(inputs + (row0 + r)*64 + quad*4);
            }
        }
    }
    __syncthreads();

    {
        int ci = tid >> 2, q = tid & 3;
        if (ci < act) {
            const float4* p = (const float4*)(xs + ci*64 + q*16);
            float s = 0.f, ss = 0.f;
            #pragma unroll
            for (int i = 0; i < 4; ++i) {
                float4 v = p[i];
                s  += (v.x + v.y) + (v.z + v.w);
                ss += (v.x*v.x + v.y*v.y) + (v.z*v.z + v.w*v.w);
            }
            ps[ci*4 + q] = s;
            pq[ci*4 + q] = ss;
        }
    }
    __syncthreads();

    if (tid < act) {
        float s  = (ps[tid*4] + ps[tid*4+1]) + (ps[tid*4+2] + ps[tid*4+3]);
        float ss = (pq[tid*4] + pq[tid*4+1]) + (pq[tid*4+2] + pq[tid*4+3]);
        float mu  = s * (1.f/64.f);
        float var = ss * (1.f/64.f) - mu*mu;
        rmu[tid] = mu;
        rrs[tid] = rsqrtf(var + LN_EPS);
    }
    __syncthreads();

    {
        int tot = act * 8;
        for (int e = tid; e < tot; e += 256) {
            int ci = e >> 3, q = e & 7;
            float mu = rmu[ci], rs = rrs[ci];
            float4 v0 = *(float4*)(xs + ci*64 + q*8);
            float4 v1 = *(float4*)(xs + ci*64 + q*8 + 4);
            float4 w0 = __ldg((const float4*)lnw + 2*q);
            float4 w1 = __ldg((const float4*)lnw + 2*q + 1);
            float4 b0 = __ldg((const float4*)lnb + 2*q);
            float4 b1 = __ldg((const float4*)lnb + 2*q + 1);
            __half2 h[4];
            h[0] = __floats2half2_rn((v0.x - mu)*rs*w0.x + b0.x, (v0.y - mu)*rs*w0.y + b0.y);
            h[1] = __floats2half2_rn((v0.z - mu)*rs*w0.z + b0.z, (v0.w - mu)*rs*w0.w + b0.w);
            h[2] = __floats2half2_rn((v1.x - mu)*rs*w1.x + b1.x, (v1.y - mu)*rs*w1.y + b1.y);
            h[3] = __floats2half2_rn((v1.z - mu)*rs*w1.z + b1.z, (v1.w - mu)*rs*w1.w + b1.w);
            *(uint4*)(xh + ci*128 + ((q ^ (ci & 7)) << 4)) = *(uint4*)h;
        }
    }
    __syncthreads();

    {
        int wsel = warp >> 2;
        int n0 = (warp & 3) * 16;
        const __half* wh = wsel ? wv : wk;
        const float*  bias = wsel ? bv : bk;
        __half* dst = wsel ? g_vh : g_kh;

        uint32_t xh_base = smem_u32(xh);
        int j = lane >> 2, kb = (lane & 3) * 2;
        float acc[2][4][4];
        #pragma unroll
        for (int ns = 0; ns < 2; ++ns)
            #pragma unroll
            for (int mt = 0; mt < 4; ++mt)
                #pragma unroll
                for (int i = 0; i < 4; ++i) acc[ns][mt][i] = 0.f;

        #pragma unroll
        for (int ks = 0; ks < 4; ++ks) {
            uint32_t b0a = *(const uint32_t*)(wh + (n0 + j)*WSTR + 16*ks + kb);
            uint32_t b1a = *(const uint32_t*)(wh + (n0 + j)*WSTR + 16*ks + kb + 8);
            uint32_t b0b = *(const uint32_t*)(wh + (n0 + 8 + j)*WSTR + 16*ks + kb);
            uint32_t b1b = *(const uint32_t*)(wh + (n0 + 8 + j)*WSTR + 16*ks + kb + 8);
            #pragma unroll
            for (int mt = 0; mt < 4; ++mt) {
                int lr = mt*16 + (lane & 15);
                int qq = 2*ks + (lane >> 4);
                uint32_t addr = xh_base + lr*128 + ((qq ^ (lr & 7)) << 4);
                uint32_t a0, a1, a2, a3;
                asm volatile("ldmatrix.sync.aligned.m8n8.x4.shared.b16 {%0,%1,%2,%3}, [%4];"
                             : "=r"(a0), "=r"(a1), "=r"(a2), "=r"(a3) : "r"(addr));
                asm volatile("mma.sync.aligned.m16n8k16.row.col.f32.f16.f16.f32 "
                             "{%0,%1,%2,%3}, {%4,%5,%6,%7}, {%8,%9}, {%0,%1,%2,%3};"
                             : "+f"(acc[0][mt][0]), "+f"(acc[0][mt][1]),
                               "+f"(acc[0][mt][2]), "+f"(acc[0][mt][3])
                             : "r"(a0), "r"(a1), "r"(a2), "r"(a3), "r"(b0a), "r"(b1a));
                asm volatile("mma.sync.aligned.m16n8k16.row.col.f32.f16.f16.f32 "
                             "{%0,%1,%2,%3}, {%4,%5,%6,%7}, {%8,%9}, {%0,%1,%2,%3};"
                             : "+f"(acc[1][mt][0]), "+f"(acc[1][mt][1]),
                               "+f"(acc[1][mt][2]), "+f"(acc[1][mt][3])
                             : "r"(a0), "r"(a1), "r"(a2), "r"(a3), "r"(b0b), "r"(b1b));
            }
        }

        int trow = lane >> 2;
        #pragma unroll
        for (int ns = 0; ns < 2; ++ns) {
            int c = n0 + ns*8 + (lane & 3)*2;
            float bx = __ldg(bias + c), by = __ldg(bias + c + 1);
            #pragma unroll
            for (int mt = 0; mt < 4; ++mt) {
                int r0 = mt*16 + trow;
                int r1 = r0 + 8;
                if (r0 < act) {
                    __half2 hv = __floats2half2_rn(acc[ns][mt][0] + bx, acc[ns][mt][1] + by);
                    *(__half2*)(dst + (row0 + r0)*64 + c) = hv;
                }
                if (r1 < act) {
                    __half2 hv = __floats2half2_rn(acc[ns][mt][2] + bx, acc[ns][mt][3] + by);
                    *(__half2*)(dst + (row0 + r1)*64 + c) = hv;
                }
            }
        }
    }
}

// ---------------- LN over slot rows ----------------
__device__ __forceinline__ void lnrows(const float* in, float* out,
                                       const float* __restrict__ w,
                                       const float* __restrict__ bia, int tid, int nrows) {
    int wp = tid >> 5, lane = tid & 31;
    if (wp >= nrows) return;
    const float* p = in + wp*64;
    float v0 = p[lane], v1 = p[lane+32];
    float s = v0 + v1;
    #pragma unroll
    for (int o = 16; o; o >>= 1) s += __shfl_xor_sync(~0u, s, o);
    float mu = s * (1.f/64.f);
    float d0 = v0 - mu, d1 = v1 - mu;
    float q = d0*d0 + d1*d1;
    #pragma unroll
    for (int o = 16; o; o >>= 1) q += __shfl_xor_sync(~0u, q, o);
    float rs = rsqrtf(q * (1.f/64.f) + LN_EPS);
    out[wp*64 + lane]      = d0*rs*w[lane] + bia[lane];
    out[wp*64 + lane + 32] = d1*rs*w[lane+32] + bia[lane+32];
}

// ---------------- attention: HMMA phase A + HMMA phase C ----------------
__global__ __launch_bounds__(256)
void k_attn() {
    __shared__ __align__(16) char sbuf[32*1024];        // k-stage, then v-stage
    __shared__ __align__(16) char dU[16*ASTR*2];        // fp32 dots (8224B) then fp16 attH (8704B)
    __shared__ __align__(4)  __half qh[8*QSTR];
    __shared__ int cnts[4];

    float*  dots = (float*)dU;
    __half* attH = (__half*)dU;

    int b = blockIdx.y, chunk = blockIdx.x;
    int tid = threadIdx.x;
    int warp = tid >> 5, lane = tid & 31;

    if (tid < 4) cnts[tid] = g_cnt[b*(N/TILE_R) + chunk*4 + tid];

    // stage k tile (swizzled)
    {
        const uint4* src = (const uint4*)(g_kh + ((size_t)b*N + chunk*256)*64);
        #pragma unroll
        for (int e0 = 0; e0 < 2048; e0 += 256) {
            int e = e0 + tid;
            int ci = e >> 3, q = e & 7;
            uint4 v = __ldg(src + e);
            *(uint4*)(sbuf + ci*128 + ((q ^ (ci & 7)) << 4)) = v;
        }
    }
    for (int e = tid; e < 512; e += 256) {
        int j = e >> 6, d = e & 63;
        qh[j*QSTR + d] = __float2half_rn(g_q[b*512 + e]);
    }
    __syncthreads();

    // Phase A: k·q dots via HMMA (R12 proven)
    {
        uint32_t stg_base = smem_u32(sbuf);
        int R0 = warp * 32;
        float d0[4] = {0.f,0.f,0.f,0.f};
        float d1[4] = {0.f,0.f,0.f,0.f};
        int j = lane >> 2, kb = (lane & 3) * 2;
        #pragma unroll
        for (int ks = 0; ks < 4; ++ks) {
            uint32_t b0 = *(const uint32_t*)(qh + j*QSTR + 16*ks + kb);
            uint32_t b1 = *(const uint32_t*)(qh + j*QSTR + 16*ks + kb + 8);
            #pragma unroll
            for (int tile = 0; tile < 2; ++tile) {
                int lr = R0 + tile*16 + (lane & 15);
                int qq = 2*ks + (lane >> 4);
                uint32_t addr = stg_base + lr*128 + ((qq ^ (lr & 7)) << 4);
                uint32_t a0, a1, a2, a3;
                asm volatile("ldmatrix.sync.aligned.m8n8.x4.shared.b16 {%0,%1,%2,%3}, [%4];"
                             : "=r"(a0), "=r"(a1), "=r"(a2), "=r"(a3) : "r"(addr));
                float* dd = tile ? d1 : d0;
                asm volatile("mma.sync.aligned.m16n8k16.row.col.f32.f16.f16.f32 "
                             "{%0,%1,%2,%3}, {%4,%5,%6,%7}, {%8,%9}, {%0,%1,%2,%3};"
                             : "+f"(dd[0]), "+f"(dd[1]), "+f"(dd[2]), "+f"(dd[3])
                             : "r"(a0), "r"(a1), "r"(a2), "r"(a3), "r"(b0), "r"(b1));
            }
        }
        int s = warp >> 1;
        int rbase = (warp & 1) * 32;
        int trow = lane >> 2;
        int col = (lane & 3) * 2;
        #pragma unroll
        for (int tile = 0; tile < 2; ++tile) {
            float* dd = tile ? d1 : d0;
            int r = rbase + tile*16 + trow;
            dots[(col  )*DSTR + s*64 + r    ] = dd[0];
            dots[(col+1)*DSTR + s*64 + r    ] = dd[1];
            dots[(col  )*DSTR + s*64 + r + 8] = dd[2];
            dots[(col+1)*DSTR + s*64 + r + 8] = dd[3];
        }
    }
    __syncthreads();

    // Phase B part 1: softmax into registers (reads dots); stage v into sbuf (k dead)
    float av[8];
    {
        int s = tid >> 6, r = tid & 63;
        int act = cnts[s];
        if (r < act) {
            float d[8];
            #pragma unroll
            for (int j2 = 0; j2 < 8; ++j2) d[j2] = dots[j2*DSTR + tid];
            float m = d[0];
            #pragma unroll
            for (int j2 = 1; j2 < 8; ++j2) m = fmaxf(m, d[j2]);
            float e[8], sum = 0.f;
            #pragma unroll
            for (int j2 = 0; j2 < 8; ++j2) { e[j2] = __expf(d[j2] - m); sum += e[j2]; }
            float inv = __fdividef(1.f, sum);
            #pragma unroll
            for (int j2 = 0; j2 < 8; ++j2) av[j2] = e[j2]*inv + EPSA;
        } else {
            #pragma unroll
            for (int j2 = 0; j2 < 8; ++j2) av[j2] = 0.f;
        }
    }
    {
        const uint4* src = (const uint4*)(g_vh + ((size_t)b*N + chunk*256)*64);
        #pragma unroll
        for (int e0 = 0; e0 < 2048; e0 += 256) {
            int e = e0 + tid;
            int ci = e >> 3, q = e & 7;
            uint4 v = __ldg(src + e);
            *(uint4*)(sbuf + ci*128 + ((q ^ (ci & 7)) << 4)) = v;
        }
    }
    __syncthreads();   // dots reads done everywhere -> safe to overwrite with attH

    // Phase B part 2: write fp16 att tile [16][ASTR]; zero slot rows 8..15
    #pragma unroll
    for (int j2 = 0; j2 < 8; ++j2)
        attH[j2*ASTR + tid] = __float2half_rn(av[j2]);
    for (int e = tid; e < 8*ASTR; e += 256)
        attH[8*ASTR + e] = __ushort_as_half(0);
    __syncthreads();

    // S per slot: warp j sums attH[j][0..255]
    {
        const __half2* ap = (const __half2*)(attH + warp*ASTR);
        float s = 0.f;
        #pragma unroll
        for (int i = 0; i < 4; ++i) {
            float2 f = __half22float2(ap[lane + 32*i]);
            s += f.x + f.y;
        }
        #pragma unroll
        for (int o = 16; o; o >>= 1) s += __shfl_xor_sync(~0u, s, o);
        if (lane == 0) g_Sp[(b*NB + chunk)*8 + warp] = s;
    }

    // Phase C: P = att^T · v via HMMA; warp owns dims n0 = warp*8 (full K sum, no reduction)
    {
        uint32_t vbase = smem_u32(sbuf);
        uint32_t abase = smem_u32(attH);
        float acc[4] = {0.f, 0.f, 0.f, 0.f};
        int qcol = warp;
        #pragma unroll
        for (int ks = 0; ks < 16; ++ks) {
            uint32_t aaddr = abase + (uint32_t)((lane & 15)*ASTR + ks*16 + ((lane >> 4) << 3)) * 2u;
            uint32_t a0, a1, a2, a3;
            asm volatile("ldmatrix.sync.aligned.m8n8.x4.shared.b16 {%0,%1,%2,%3}, [%4];"
                         : "=r"(a0), "=r"(a1), "=r"(a2), "=r"(a3) : "r"(aaddr));
            int krow = ks*16 + (lane & 15);
            uint32_t baddr = vbase + krow*128 + ((qcol ^ (krow & 7)) << 4);
            uint32_t bb0, bb1;
            asm volatile("ldmatrix.sync.aligned.m8n8.x2.trans.shared.b16 {%0,%1}, [%2];"
                         : "=r"(bb0), "=r"(bb1) : "r"(baddr));
            asm volatile("mma.sync.aligned.m16n8k16.row.col.f32.f16.f16.f32 "
                         "{%0,%1,%2,%3}, {%4,%5,%6,%7}, {%8,%9}, {%0,%1,%2,%3};"
                         : "+f"(acc[0]), "+f"(acc[1]), "+f"(acc[2]), "+f"(acc[3])
                         : "r"(a0), "r"(a1), "r"(a2), "r"(a3), "r"(bb0), "r"(bb1));
        }
        // D rows 0..7 = slots; rows 8..15 (acc[2],acc[3]) are padding
        int slot = lane >> 2;
        int c = warp*8 + (lane & 3)*2;
        float* pp = g_Pp + ((size_t)b*NB + chunk)*512 + slot*64 + c;
        pp[0] = acc[0];
        pp[1] = acc[1];
    }
}

// ---------------- slot update: explicit load-batching (R13 proven) ----------------
__global__ __launch_bounds__(256, 2)
void k_update(const float* __restrict__ b_ih, const float* __restrict__ b_hh,
              const float* __restrict__ b1, const float* __restrict__ b2,
              const float* __restrict__ ln_ff_w, const float* __restrict__ ln_ff_b,
              const float* __restrict__ ln_s_w, const float* __restrict__ ln_s_b,
              const float* __restrict__ bq,
              float* __restrict__ d_out, int last) {
    __shared__ float upd[256], prev[256], snew[256], ffs[256], hid[512], sfin[256], Ssm[4];
    int b = blockIdx.y, half = blockIdx.x, tid = threadIdx.x;
    int j0 = half * 4;
    int j = tid >> 6, dd = tid & 63;
    int J = j0 + j;

    if (tid < 4) {
        float v[NB];
        const float* sp = g_Sp + b*NB*8 + j0 + tid;
        #pragma unroll
        for (int p = 0; p < NB; ++p) v[p] = sp[p*8];
        float s = 0.f;
        #pragma unroll
        for (int p = 0; p < NB; ++p) s += v[p];
        Ssm[tid] = s;
    }
    float pr;
    {
        float v[NB];
        const float* pp = g_Pp + (size_t)b*NB*512 + J*64 + dd;
        #pragma unroll
        for (int p = 0; p < NB; ++p) v[p] = pp[p*512];
        float s = 0.f;
        #pragma unroll
        for (int p = 0; p < NB; ++p) s += v[p];
        pr = s;
        prev[tid] = g_slots[b*512 + J*64 + dd];
    }
    __syncthreads();
    upd[tid] = pr / Ssm[j];
    __syncthreads();

    {
        const float* uj = upd + j*64;
        const float* hj = prev + j*64;
        float xr = b_ih[dd], xz = b_ih[64+dd], xn = b_ih[128+dd];
        float hr = b_hh[dd], hz = b_hh[64+dd], hn = b_hh[128+dd];
        #pragma unroll
        for (int db = 0; db < 64; db += 8) {
            float4 wa8[8];
            float2 wb8[8];
            #pragma unroll
            for (int t = 0; t < 8; ++t) wa8[t] = __ldg(g_WgA + (db+t)*64 + dd);
            #pragma unroll
            for (int t = 0; t < 8; ++t) wb8[t] = __ldg(g_WgB + (db+t)*64 + dd);
            #pragma unroll
            for (int t = 0; t < 8; ++t) {
                float uu = uj[db+t], hh = hj[db+t];
                xr += uu*wa8[t].x; xz += uu*wa8[t].y; xn += uu*wa8[t].z;
                hr += hh*wa8[t].w; hz += hh*wb8[t].x; hn += hh*wb8[t].y;
            }
        }
        float rg = 1.f/(1.f + __expf(-(xr + hr)));
        float zg = 1.f/(1.f + __expf(-(xz + hz)));
        float t2 = __expf(2.f*(xn + rg*hn));
        float nn = 1.f - 2.f/(t2 + 1.f);
        snew[tid] = (1.f - zg)*nn + zg*prev[tid];
    }
    __syncthreads();
    lnrows(snew, ffs, ln_ff_w, ln_ff_b, tid, 4);
    __syncthreads();
    {
        int h2 = dd;
        float a0 = b1[2*h2], a1 = b1[2*h2+1];
        const float* fj = ffs + j*64;
        #pragma unroll
        for (int db = 0; db < 64; db += 16) {
            float2 w8[16];
            #pragma unroll
            for (int t = 0; t < 16; ++t) w8[t] = __ldg(g_W1p + (db+t)*64 + h2);
            #pragma unroll
            for (int t = 0; t < 16; ++t) {
                float f = fj[db+t];
                a0 += f*w8[t].x; a1 += f*w8[t].y;
            }
        }
        hid[j*128 + 2*h2]   = fmaxf(a0, 0.f);
        hid[j*128 + 2*h2+1] = fmaxf(a1, 0.f);
    }
    __syncthreads();
    {
        float acc = b2[dd];
        const float2* hj2 = (const float2*)(hid + j*128);
        #pragma unroll
        for (int hb = 0; hb < 64; hb += 16) {
            float2 w8[16];
            #pragma unroll
            for (int t = 0; t < 16; ++t) w8[t] = __ldg(g_W2p + (hb+t)*64 + dd);
            #pragma unroll
            for (int t = 0; t < 16; ++t) {
                float2 hv = hj2[hb+t];
                acc += hv.x*w8[t].x + hv.y*w8[t].y;
            }
        }
        float o = snew[tid] + acc;
        sfin[tid] = o;
        g_slots[b*512 + J*64 + dd] = o;
        if (last) d_out[b*512 + J*64 + dd] = o;
    }
    if (!last) {
        __syncthreads();
        lnrows(sfin, ffs, ln_s_w, ln_s_b, tid, 4);
        __syncthreads();
        {
            float acc = bq[dd];
            const float2* sj2 = (const float2*)(ffs + j*64);
            #pragma unroll
            for (int db = 0; db < 32; db += 16) {
                float2 w8[16];
                #pragma unroll
                for (int t = 0; t < 16; ++t) w8[t] = __ldg(g_Wqp + (db+t)*64 + dd);
                #pragma unroll
                for (int t = 0; t < 16; ++t) {
                    float2 s2 = sj2[db+t];
                    acc += s2.x*w8[t].x + s2.y*w8[t].y;
                }
            }
            g_q[b*512 + J*64 + dd] = acc * SCALE;
        }
    }
}

// ---------------- launch ----------------
extern "C" void kernel_launch(void* const* d_in, const int* in_sizes, int n_in,
                              void* d_out, int out_size) {
    const float* inputs     = (const float*)d_in[0];
    const int*   mask       = (const int*)  d_in[1];
    const float* noise      = (const float*)d_in[2];
    const float* slots_mu   = (const float*)d_in[3];
    const float* slots_sig  = (const float*)d_in[4];
    const float* Wq         = (const float*)d_in[5];
    const float* bq         = (const float*)d_in[6];
    const float* Wk         = (const float*)d_in[7];
    const float* bk         = (const float*)d_in[8];
    const float* Wv         = (const float*)d_in[9];
    const float* bv         = (const float*)d_in[10];
    const float* W_ih       = (const float*)d_in[11];
    const float* b_ih       = (const float*)d_in[12];
    const float* W_hh       = (const float*)d_in[13];
    const float* b_hh       = (const float*)d_in[14];
    const float* W1         = (const float*)d_in[15];
    const float* b1         = (const float*)d_in[16];
    const float* W2         = (const float*)d_in[17];
    const float* b2         = (const float*)d_in[18];
    const float* ln_in_w    = (const float*)d_in[19];
    const float* ln_in_b    = (const float*)d_in[20];
    const float* ln_s_w     = (const float*)d_in[21];
    const float* ln_s_b     = (const float*)d_in[22];
    const float* ln_ff_w    = (const float*)d_in[23];
    const float* ln_ff_b    = (const float*)d_in[24];
    float* out = (float*)d_out;

    k_prep_init<<<64, 256>>>(Wk, Wv, W_ih, W_hh, W1, W2, Wq,
                             noise, slots_mu, slots_sig, ln_s_w, ln_s_b, bq);
    k_ln_kv<<<(B*N)/TILE_R, 256>>>(inputs, mask, bk, bv, ln_in_w, ln_in_b);
    for (int it = 0; it < ITERS; ++it) {
        k_attn<<<dim3(NB, B), 256>>>();
        k_update<<<dim3(2, B), 256>>>(b_ih, b_hh, b1, b2, ln_ff_w, ln_ff_b,
                                      ln_s_w, ln_s_b, bq, out, it == ITERS-1 ? 1 : 0);
    }
}